// round 1
// baseline (speedup 1.0000x reference)
#include <cuda_runtime.h>
#include <math.h>

// ---------------------------------------------------------------------------
// Problem constants
// ---------------------------------------------------------------------------
#define B_    8
#define S_    1024
#define D_    1024
#define H_    16
#define DH_   64
#define FF_   4096
#define TOK   (B_ * S_)          // 8192 tokens

// ---------------------------------------------------------------------------
// Scratch (static device globals — no runtime allocation allowed)
// ---------------------------------------------------------------------------
__device__ float g_ln  [(size_t)TOK * D_];       // 32 MB  (LN output, reused)
__device__ float g_qkv [(size_t)TOK * 3 * D_];   // 96 MB
__device__ float g_attn[(size_t)TOK * D_];       // 32 MB
__device__ float g_x2  [(size_t)TOK * D_];       // 32 MB  (x + attn proj)
__device__ float g_ffn [(size_t)TOK * FF_];      // 128 MB

// ---------------------------------------------------------------------------
// LayerNorm: one block per token (row of 1024), 256 threads, float4 per thread
// ---------------------------------------------------------------------------
__global__ __launch_bounds__(256)
void ln_kernel(const float* __restrict__ x,
               const float* __restrict__ gw,
               const float* __restrict__ bw,
               float* __restrict__ out)
{
    __shared__ float red[16];
    const int row = blockIdx.x;
    const int tid = threadIdx.x;

    const float4 v = ((const float4*)(x + (size_t)row * D_))[tid];
    float s  = v.x + v.y + v.z + v.w;
    float ss = v.x*v.x + v.y*v.y + v.z*v.z + v.w*v.w;

    #pragma unroll
    for (int o = 16; o; o >>= 1) {
        s  += __shfl_xor_sync(0xffffffffu, s,  o);
        ss += __shfl_xor_sync(0xffffffffu, ss, o);
    }
    const int wid = tid >> 5, lid = tid & 31;
    if (lid == 0) { red[wid] = s; red[8 + wid] = ss; }
    __syncthreads();

    float sum = 0.f, sq = 0.f;
    #pragma unroll
    for (int i = 0; i < 8; i++) { sum += red[i]; sq += red[8 + i]; }

    const float mu  = sum * (1.0f / D_);
    const float var = sq  * (1.0f / D_) - mu * mu;
    const float rs  = rsqrtf(var + 1e-5f);

    const float4 g4 = ((const float4*)gw)[tid];
    const float4 b4 = ((const float4*)bw)[tid];
    float4 o;
    o.x = (v.x - mu) * rs * g4.x + b4.x;
    o.y = (v.y - mu) * rs * g4.y + b4.y;
    o.z = (v.z - mu) * rs * g4.z + b4.z;
    o.w = (v.w - mu) * rs * g4.w + b4.w;
    ((float4*)(out + (size_t)row * D_))[tid] = o;
}

// ---------------------------------------------------------------------------
// SGEMM (TN): C[M,N] = A[M,K] * B[N,K]^T + bias[N]  (+ epilogue)
// Block tile 128x128, K-tile 16, 256 threads, 8x8 per-thread micro-tile.
// ---------------------------------------------------------------------------
enum { EPI_BIAS = 0, EPI_BIAS_RES = 1, EPI_GELU = 2 };

__device__ __forceinline__ float gelu_tanh(float x)
{
    const float u = 0.7978845608028654f * (x + 0.044715f * x * x * x);
    return 0.5f * x * (1.0f + tanhf(u));
}

template <int EPI>
__global__ __launch_bounds__(256)
void sgemm_tn(const float* __restrict__ A, const float* __restrict__ Bm,
              const float* __restrict__ bias, const float* __restrict__ resid,
              float* __restrict__ C, int M, int N, int K)
{
    __shared__ float As[16][128];
    __shared__ float Bs[16][128];

    const int tid = threadIdx.x;
    const int tx  = tid & 15;
    const int ty  = tid >> 4;
    const int m0  = blockIdx.y * 128;
    const int n0  = blockIdx.x * 128;

    const int lr = tid >> 2;          // 0..63
    const int lc = (tid & 3) << 2;    // 0,4,8,12

    const float* Ag = A  + (size_t)(m0 + lr) * K + lc;
    const float* Bg = Bm + (size_t)(n0 + lr) * K + lc;

    float acc[8][8];
    #pragma unroll
    for (int i = 0; i < 8; i++)
        #pragma unroll
        for (int j = 0; j < 8; j++) acc[i][j] = 0.f;

    for (int k0 = 0; k0 < K; k0 += 16) {
        const float4 a0 = *(const float4*)(Ag + k0);
        const float4 a1 = *(const float4*)(Ag + (size_t)64 * K + k0);
        const float4 b0 = *(const float4*)(Bg + k0);
        const float4 b1 = *(const float4*)(Bg + (size_t)64 * K + k0);

        __syncthreads();
        As[lc+0][lr]    = a0.x; As[lc+1][lr]    = a0.y; As[lc+2][lr]    = a0.z; As[lc+3][lr]    = a0.w;
        As[lc+0][lr+64] = a1.x; As[lc+1][lr+64] = a1.y; As[lc+2][lr+64] = a1.z; As[lc+3][lr+64] = a1.w;
        Bs[lc+0][lr]    = b0.x; Bs[lc+1][lr]    = b0.y; Bs[lc+2][lr]    = b0.z; Bs[lc+3][lr]    = b0.w;
        Bs[lc+0][lr+64] = b1.x; Bs[lc+1][lr+64] = b1.y; Bs[lc+2][lr+64] = b1.z; Bs[lc+3][lr+64] = b1.w;
        __syncthreads();

        #pragma unroll
        for (int kk = 0; kk < 16; kk++) {
            const float4 aA = *(const float4*)&As[kk][ty * 8];
            const float4 aB = *(const float4*)&As[kk][ty * 8 + 4];
            const float4 bA = *(const float4*)&Bs[kk][tx * 8];
            const float4 bB = *(const float4*)&Bs[kk][tx * 8 + 4];
            const float a[8] = {aA.x, aA.y, aA.z, aA.w, aB.x, aB.y, aB.z, aB.w};
            const float b[8] = {bA.x, bA.y, bA.z, bA.w, bB.x, bB.y, bB.z, bB.w};
            #pragma unroll
            for (int i = 0; i < 8; i++)
                #pragma unroll
                for (int j = 0; j < 8; j++)
                    acc[i][j] = fmaf(a[i], b[j], acc[i][j]);
        }
    }

    #pragma unroll
    for (int i = 0; i < 8; i++) {
        const int m = m0 + ty * 8 + i;
        #pragma unroll
        for (int j = 0; j < 8; j++) {
            const int n = n0 + tx * 8 + j;
            float v = acc[i][j] + bias[n];
            if (EPI == EPI_GELU)     v = gelu_tanh(v);
            if (EPI == EPI_BIAS_RES) v += resid[(size_t)m * N + n];
            C[(size_t)m * N + n] = v;
        }
    }
}

// ---------------------------------------------------------------------------
// Causal flash attention, fp32.
// Grid: (S/64, B*H). 64 threads/block; thread t owns query row t of the tile.
// q and o accumulators in registers; K/V 64x64 tiles in smem; online softmax
// processed in two 32-wide chunks to bound register pressure.
// ---------------------------------------------------------------------------
__global__ __launch_bounds__(64)
void attn_kernel(const float* __restrict__ qkv, float* __restrict__ attn_out)
{
    __shared__ float k_s[64][68];   // padded (16B-aligned rows, conflict-free staging)
    __shared__ float v_s[64][64];

    const int qt = blockIdx.x;              // 0..15 query tile
    const int bh = blockIdx.y;              // 0..127
    const int b  = bh >> 4;
    const int h  = bh & 15;
    const int t  = threadIdx.x;             // 0..63  = query row in tile

    const size_t seq_base = (size_t)b * S_ * (3 * D_);
    const size_t head_off = (size_t)h * DH_;

    // q row -> registers
    float q[64];
    {
        const float* qp = qkv + seq_base + head_off + (size_t)(qt * 64 + t) * (3 * D_);
        #pragma unroll
        for (int d = 0; d < 64; d += 4) {
            const float4 u = *(const float4*)(qp + d);
            q[d] = u.x; q[d+1] = u.y; q[d+2] = u.z; q[d+3] = u.w;
        }
    }

    float o[64];
    #pragma unroll
    for (int d = 0; d < 64; d++) o[d] = 0.f;
    float m = -1e30f, l = 0.f;

    for (int kt = 0; kt <= qt; kt++) {
        // cooperative load of K,V tile [64 x 64]
        const float* kp = qkv + seq_base + D_     + head_off + (size_t)(kt * 64) * (3 * D_);
        const float* vp = qkv + seq_base + 2 * D_ + head_off + (size_t)(kt * 64) * (3 * D_);
        #pragma unroll 4
        for (int i = t; i < 64 * 16; i += 64) {
            const int r = i >> 4;
            const int c = (i & 15) << 2;
            const float4 kv = *(const float4*)(kp + (size_t)r * (3 * D_) + c);
            *(float4*)&k_s[r][c] = kv;
            const float4 vv = *(const float4*)(vp + (size_t)r * (3 * D_) + c);
            *(float4*)&v_s[r][c] = vv;
        }
        __syncthreads();

        const bool diag = (kt == qt);
        #pragma unroll
        for (int half = 0; half < 2; half++) {
            const int kbase = half * 32;
            float s[32];
            float mt = -1e30f;
            #pragma unroll 2
            for (int kc = 0; kc < 32; kc++) {
                const float4* krow = (const float4*)k_s[kbase + kc];
                float d0 = 0.f, d1 = 0.f, d2 = 0.f, d3 = 0.f;
                #pragma unroll
                for (int d4 = 0; d4 < 16; d4++) {
                    const float4 kv = krow[d4];
                    d0 = fmaf(q[4*d4+0], kv.x, d0);
                    d1 = fmaf(q[4*d4+1], kv.y, d1);
                    d2 = fmaf(q[4*d4+2], kv.z, d2);
                    d3 = fmaf(q[4*d4+3], kv.w, d3);
                }
                float sc = (d0 + d1 + d2 + d3) * 0.125f;   // 1/sqrt(64)
                if (diag && (kbase + kc) > t) sc = -1e30f;
                s[kc] = sc;
                mt = fmaxf(mt, sc);
            }
            const float m_new = fmaxf(m, mt);
            const float corr  = __expf(m - m_new);
            l *= corr;
            #pragma unroll
            for (int d = 0; d < 64; d++) o[d] *= corr;
            #pragma unroll 2
            for (int kc = 0; kc < 32; kc++) {
                const float p = __expf(s[kc] - m_new);
                l += p;
                const float4* vrow = (const float4*)v_s[kbase + kc];
                #pragma unroll
                for (int d4 = 0; d4 < 16; d4++) {
                    const float4 vv = vrow[d4];
                    o[4*d4+0] = fmaf(p, vv.x, o[4*d4+0]);
                    o[4*d4+1] = fmaf(p, vv.y, o[4*d4+1]);
                    o[4*d4+2] = fmaf(p, vv.z, o[4*d4+2]);
                    o[4*d4+3] = fmaf(p, vv.w, o[4*d4+3]);
                }
            }
            m = m_new;
        }
        __syncthreads();   // before next iteration overwrites tiles
    }

    // normalize + stage through smem for coalesced store
    const float inv_l = 1.0f / l;
    #pragma unroll
    for (int d4 = 0; d4 < 16; d4++) {
        float4 w;
        w.x = o[4*d4+0] * inv_l;
        w.y = o[4*d4+1] * inv_l;
        w.z = o[4*d4+2] * inv_l;
        w.w = o[4*d4+3] * inv_l;
        *(float4*)&k_s[t][4*d4] = w;
    }
    __syncthreads();
    float* op = attn_out + ((size_t)b * S_ + qt * 64) * D_ + head_off;
    #pragma unroll 4
    for (int i = t; i < 64 * 16; i += 64) {
        const int r = i >> 4;
        const int c = (i & 15) << 2;
        float4 w;
        w.x = k_s[r][c]; w.y = k_s[r][c+1]; w.z = k_s[r][c+2]; w.w = k_s[r][c+3];
        *(float4*)(op + (size_t)r * D_ + c) = w;
    }
}

// ---------------------------------------------------------------------------
// Launch
// ---------------------------------------------------------------------------
extern "C" void kernel_launch(void* const* d_in, const int* in_sizes, int n_in,
                              void* d_out, int out_size)
{
    const float* x     = (const float*)d_in[0];
    const float* ln1_g = (const float*)d_in[1];
    const float* ln1_b = (const float*)d_in[2];
    const float* w_qkv = (const float*)d_in[3];
    const float* b_qkv = (const float*)d_in[4];
    const float* w_o   = (const float*)d_in[5];
    const float* b_o   = (const float*)d_in[6];
    const float* ln2_g = (const float*)d_in[7];
    const float* ln2_b = (const float*)d_in[8];
    const float* w1    = (const float*)d_in[9];
    const float* b1    = (const float*)d_in[10];
    const float* w2    = (const float*)d_in[11];
    const float* b2    = (const float*)d_in[12];
    float* out = (float*)d_out;

    static float* p_ln   = nullptr;
    static float* p_qkv  = nullptr;
    static float* p_attn = nullptr;
    static float* p_x2   = nullptr;
    static float* p_ffn  = nullptr;
    if (!p_ln) {
        void* p;
        cudaGetSymbolAddress(&p, g_ln);   p_ln   = (float*)p;
        cudaGetSymbolAddress(&p, g_qkv);  p_qkv  = (float*)p;
        cudaGetSymbolAddress(&p, g_attn); p_attn = (float*)p;
        cudaGetSymbolAddress(&p, g_x2);   p_x2   = (float*)p;
        cudaGetSymbolAddress(&p, g_ffn);  p_ffn  = (float*)p;
    }

    // 1. LN1
    ln_kernel<<<TOK, 256>>>(x, ln1_g, ln1_b, p_ln);

    // 2. QKV projection: [8192,1024] x [3072,1024]^T
    sgemm_tn<EPI_BIAS><<<dim3(3 * D_ / 128, TOK / 128), 256>>>(
        p_ln, w_qkv, b_qkv, nullptr, p_qkv, TOK, 3 * D_, D_);

    // 3. causal attention
    attn_kernel<<<dim3(S_ / 64, B_ * H_), 64>>>(p_qkv, p_attn);

    // 4. output projection + residual: x2 = x + attn @ w_o^T + b_o
    sgemm_tn<EPI_BIAS_RES><<<dim3(D_ / 128, TOK / 128), 256>>>(
        p_attn, w_o, b_o, x, p_x2, TOK, D_, D_);

    // 5. LN2
    ln_kernel<<<TOK, 256>>>(p_x2, ln2_g, ln2_b, p_ln);

    // 6. FFN up + GELU
    sgemm_tn<EPI_GELU><<<dim3(FF_ / 128, TOK / 128), 256>>>(
        p_ln, w1, b1, nullptr, p_ffn, TOK, FF_, D_);

    // 7. FFN down + residual -> out
    sgemm_tn<EPI_BIAS_RES><<<dim3(D_ / 128, TOK / 128), 256>>>(
        p_ffn, w2, b2, p_x2, out, TOK, D_, FF_);
}

// round 3
// speedup vs baseline: 1.8624x; 1.8624x over previous
#include <cuda_runtime.h>
#include <cuda_bf16.h>
#include <math.h>
#include <stdint.h>

// ---------------------------------------------------------------------------
// Per-compilation-pass feature detection: tcgen05 is only legal on
// sm_100a/sm_103a/sm_1xxf targets. The harness also compiles a plain
// compute_103 pass, which must get the portable fallback body.
// ---------------------------------------------------------------------------
#if defined(__CUDA_ARCH__)
# if defined(__CUDA_ARCH_FEAT_SM103_ALL) || defined(__CUDA_ARCH_FEAT_SM100_ALL) || \
     (defined(__CUDA_ARCH_FAMILY_SPECIFIC__) && (__CUDA_ARCH_FAMILY_SPECIFIC__ >= 1000))
#  define HAS_TCGEN05 1
# else
#  define HAS_TCGEN05 0
# endif
#else
# define HAS_TCGEN05 0
#endif

// ---------------------------------------------------------------------------
// Problem constants
// ---------------------------------------------------------------------------
#define B_    8
#define S_    1024
#define D_    1024
#define H_    16
#define DH_   64
#define FF_   4096
#define TOK   (B_ * S_)          // 8192 tokens

// ---------------------------------------------------------------------------
// Scratch (static device globals — no runtime allocation allowed)
// ---------------------------------------------------------------------------
__device__ float g_qkv[(size_t)TOK * 3 * D_];
__device__ float g_x2 [(size_t)TOK * D_];
__device__ __nv_bfloat16 g_act_hi[(size_t)TOK * D_];
__device__ __nv_bfloat16 g_act_lo[(size_t)TOK * D_];
__device__ __nv_bfloat16 g_big_hi[(size_t)TOK * FF_];
__device__ __nv_bfloat16 g_big_lo[(size_t)TOK * FF_];
__device__ __nv_bfloat16 g_wqkv_h[(size_t)3 * D_ * D_];
__device__ __nv_bfloat16 g_wqkv_l[(size_t)3 * D_ * D_];
__device__ __nv_bfloat16 g_wo_h[(size_t)D_ * D_];
__device__ __nv_bfloat16 g_wo_l[(size_t)D_ * D_];
__device__ __nv_bfloat16 g_w1_h[(size_t)FF_ * D_];
__device__ __nv_bfloat16 g_w1_l[(size_t)FF_ * D_];
__device__ __nv_bfloat16 g_w2_h[(size_t)D_ * FF_];
__device__ __nv_bfloat16 g_w2_l[(size_t)D_ * FF_];

// ---------------------------------------------------------------------------
// tcgen05 helpers (only in arch-specific passes)
// ---------------------------------------------------------------------------
#if HAS_TCGEN05
__device__ __forceinline__ uint32_t smem_u32_of(const void* p) {
    uint32_t a;
    asm("{ .reg .u64 t; cvta.to.shared.u64 t, %1; cvt.u32.u64 %0, t; }" : "=r"(a) : "l"(p));
    return a;
}
__device__ __forceinline__ bool elect_one() {
    uint32_t pred;
    asm volatile("{\n\t.reg .pred p;\n\telect.sync _|p, 0xFFFFFFFF;\n\tselp.b32 %0, 1, 0, p;\n\t}"
                 : "=r"(pred));
    return pred != 0;
}
__device__ __forceinline__ void cp16(uint32_t dst, const void* src) {
    asm volatile("cp.async.cg.shared.global [%0], [%1], 16;" :: "r"(dst), "l"(src));
}
__device__ __forceinline__ uint32_t sw128(uint32_t off) { return off ^ ((off >> 3) & 0x70); }

__device__ __forceinline__ uint64_t smem_desc(uint32_t addr) {
    constexpr uint64_t BASE = (uint64_t(2) << 61)   // SW128
                            | (uint64_t(1) << 46)   // Blackwell version
                            | (uint64_t(64) << 32)  // SBO = 64 (1024B atom stride)
                            | (uint64_t(1) << 16);  // LBO = 1
    return BASE | ((uint64_t)(addr >> 4) & 0x3FFF);
}
// idesc: kind::f16, d=f32, a=bf16, b=bf16, M=128, N=128
#define GEMM_IDESC ((1u<<4) | (1u<<7) | (1u<<10) | ((128u/8)<<17) | ((128u/16)<<24))

__device__ __forceinline__ void mma_f16_ss(uint32_t d, uint64_t a, uint64_t b,
                                           uint32_t idesc, bool acc) {
    uint32_t e = acc ? 1u : 0u;
    asm volatile(
        "{\n\t.reg .pred p;\n\t"
        "setp.ne.u32 p, %4, 0;\n\t"
        "tcgen05.mma.cta_group::1.kind::f16 [%0], %1, %2, %3, {%5, %5, %5, %5}, p;\n\t}"
        :: "r"(d), "l"(a), "l"(b), "r"(idesc), "r"(e), "r"(0u) : "memory");
}
__device__ __forceinline__ void mbar_init(uint32_t addr, uint32_t cnt) {
    asm volatile("mbarrier.init.shared.b64 [%0], %1;" :: "r"(addr), "r"(cnt) : "memory");
}
__device__ __forceinline__ void mbar_wait(uint32_t addr, uint32_t parity) {
    asm volatile(
        "{\n\t.reg .pred P;\n\t"
        "W%=:\n\t"
        "mbarrier.try_wait.parity.acquire.cta.shared::cta.b64 P, [%0], %1, 0x989680;\n\t"
        "@!P bra W%=;\n\t}"
        :: "r"(addr), "r"(parity) : "memory");
}

#define TC_ALLOC(sm, n)   asm volatile("tcgen05.alloc.cta_group::1.sync.aligned.shared::cta.b32 [%0], %1;" :: "r"(sm), "r"(n) : "memory")
#define TC_RELINQ()       asm volatile("tcgen05.relinquish_alloc_permit.cta_group::1.sync.aligned;")
#define TC_DEALLOC(t, n)  asm volatile("tcgen05.dealloc.cta_group::1.sync.aligned.b32 %0, %1;" :: "r"(t), "r"(n))
#define TC_COMMIT(mb)     asm volatile("tcgen05.commit.cta_group::1.mbarrier::arrive::one.shared::cluster.b64 [%0];" :: "r"(mb) : "memory")
#define TC_FENCE_AFTER()  asm volatile("tcgen05.fence::after_thread_sync;" ::: "memory")
#define TC_FENCE_BEFORE() asm volatile("tcgen05.fence::before_thread_sync;" ::: "memory")
#define TC_WAIT_LD()      asm volatile("tcgen05.wait::ld.sync.aligned;" ::: "memory")
#define CP_COMMIT()       asm volatile("cp.async.commit_group;" ::: "memory")
#define FENCE_ASYNC()     asm volatile("fence.proxy.async.shared::cta;" ::: "memory")

#define TC_LD_X32(r, t) \
    asm volatile( \
        "tcgen05.ld.sync.aligned.32x32b.x32.b32 " \
        "{%0, %1, %2, %3, %4, %5, %6, %7, " \
        " %8, %9, %10, %11, %12, %13, %14, %15, " \
        " %16, %17, %18, %19, %20, %21, %22, %23, " \
        " %24, %25, %26, %27, %28, %29, %30, %31}, [%32];" \
        : "=r"((r)[0]),  "=r"((r)[1]),  "=r"((r)[2]),  "=r"((r)[3]), \
          "=r"((r)[4]),  "=r"((r)[5]),  "=r"((r)[6]),  "=r"((r)[7]), \
          "=r"((r)[8]),  "=r"((r)[9]),  "=r"((r)[10]), "=r"((r)[11]), \
          "=r"((r)[12]), "=r"((r)[13]), "=r"((r)[14]), "=r"((r)[15]), \
          "=r"((r)[16]), "=r"((r)[17]), "=r"((r)[18]), "=r"((r)[19]), \
          "=r"((r)[20]), "=r"((r)[21]), "=r"((r)[22]), "=r"((r)[23]), \
          "=r"((r)[24]), "=r"((r)[25]), "=r"((r)[26]), "=r"((r)[27]), \
          "=r"((r)[28]), "=r"((r)[29]), "=r"((r)[30]), "=r"((r)[31]) \
        : "r"(t))
#endif  // HAS_TCGEN05

// ---------------------------------------------------------------------------
// fp32 -> bf16 (hi, lo) split helpers (portable)
// ---------------------------------------------------------------------------
__device__ __forceinline__ void split_store4(__nv_bfloat16* __restrict__ hi,
                                             __nv_bfloat16* __restrict__ lo,
                                             size_t idx, float4 v) {
    __nv_bfloat16 h0 = __float2bfloat16(v.x);
    __nv_bfloat16 h1 = __float2bfloat16(v.y);
    __nv_bfloat16 h2 = __float2bfloat16(v.z);
    __nv_bfloat16 h3 = __float2bfloat16(v.w);
    __nv_bfloat16 l0 = __float2bfloat16(v.x - __bfloat162float(h0));
    __nv_bfloat16 l1 = __float2bfloat16(v.y - __bfloat162float(h1));
    __nv_bfloat16 l2 = __float2bfloat16(v.z - __bfloat162float(h2));
    __nv_bfloat16 l3 = __float2bfloat16(v.w - __bfloat162float(h3));
    __nv_bfloat162 ha; ha.x = h0; ha.y = h1;
    __nv_bfloat162 hb; hb.x = h2; hb.y = h3;
    __nv_bfloat162 la; la.x = l0; la.y = l1;
    __nv_bfloat162 lb; lb.x = l2; lb.y = l3;
    *(__nv_bfloat162*)(hi + idx)     = ha;
    *(__nv_bfloat162*)(hi + idx + 2) = hb;
    *(__nv_bfloat162*)(lo + idx)     = la;
    *(__nv_bfloat162*)(lo + idx + 2) = lb;
}

__global__ __launch_bounds__(256)
void split_kernel(const float* __restrict__ x,
                  __nv_bfloat16* __restrict__ hi,
                  __nv_bfloat16* __restrict__ lo, int n4)
{
    int i = blockIdx.x * 256 + threadIdx.x;
    if (i < n4) {
        float4 v = ((const float4*)x)[i];
        split_store4(hi, lo, (size_t)i * 4, v);
    }
}

// ---------------------------------------------------------------------------
// LayerNorm fused with bf16 split output (portable)
// ---------------------------------------------------------------------------
__global__ __launch_bounds__(256)
void ln_split_kernel(const float* __restrict__ x,
                     const float* __restrict__ gw,
                     const float* __restrict__ bw,
                     __nv_bfloat16* __restrict__ out_hi,
                     __nv_bfloat16* __restrict__ out_lo)
{
    __shared__ float red[16];
    const int row = blockIdx.x;
    const int tid = threadIdx.x;

    const float4 v = ((const float4*)(x + (size_t)row * D_))[tid];
    float s  = v.x + v.y + v.z + v.w;
    float ss = v.x*v.x + v.y*v.y + v.z*v.z + v.w*v.w;

    #pragma unroll
    for (int o = 16; o; o >>= 1) {
        s  += __shfl_xor_sync(0xffffffffu, s,  o);
        ss += __shfl_xor_sync(0xffffffffu, ss, o);
    }
    const int wid = tid >> 5, lid = tid & 31;
    if (lid == 0) { red[wid] = s; red[8 + wid] = ss; }
    __syncthreads();

    float sum = 0.f, sq = 0.f;
    #pragma unroll
    for (int i = 0; i < 8; i++) { sum += red[i]; sq += red[8 + i]; }

    const float mu  = sum * (1.0f / D_);
    const float var = sq  * (1.0f / D_) - mu * mu;
    const float rs  = rsqrtf(var + 1e-5f);

    const float4 g4 = ((const float4*)gw)[tid];
    const float4 b4 = ((const float4*)bw)[tid];
    float4 o;
    o.x = (v.x - mu) * rs * g4.x + b4.x;
    o.y = (v.y - mu) * rs * g4.y + b4.y;
    o.z = (v.z - mu) * rs * g4.z + b4.z;
    o.w = (v.w - mu) * rs * g4.w + b4.w;
    split_store4(out_hi, out_lo, (size_t)row * D_ + tid * 4, o);
}

// ---------------------------------------------------------------------------
// GEMM (TN): C[M,N] = (Ah+Al)[M,K] * (Bh+Bl)[N,K]^T + bias  (+ epilogue)
// tcgen05 path: 128x128 tile, BK=64, 3-stage cp.async pipeline, 3-way bf16
// split accumulated in TMEM fp32.
// Fallback path (plain sm_103 pass): SIMT FFMA on recombined hi+lo.
// ---------------------------------------------------------------------------
enum { EPI_BIAS = 0, EPI_BIAS_RES = 1, EPI_GELU_SPLIT = 2 };

__device__ __forceinline__ float gelu_tanh(float x)
{
    const float u = 0.7978845608028654f * (x + 0.044715f * x * x * x);
    return 0.5f * x * (1.0f + tanhf(u));
}

#define STAGE_BYTES 65536
#define SMEM_GEMM   (1024 + 3 * STAGE_BYTES)

#if HAS_TCGEN05
__device__ __forceinline__ void stage_load(uint32_t smem_base, int s, int kt,
                                           const __nv_bfloat16* __restrict__ Ah,
                                           const __nv_bfloat16* __restrict__ Al,
                                           const __nv_bfloat16* __restrict__ Bh,
                                           const __nv_bfloat16* __restrict__ Bl,
                                           int m0, int n0, int K, int tid)
{
    const uint32_t sb = smem_base + 1024 + s * STAGE_BYTES;
    const int r = tid;                          // 0..127
    const size_t ka = (size_t)(m0 + r) * K + (size_t)kt * 64;
    const size_t kb = (size_t)(n0 + r) * K + (size_t)kt * 64;
    const __nv_bfloat16* pah = Ah + ka;
    const __nv_bfloat16* pal = Al + ka;
    const __nv_bfloat16* pbh = Bh + kb;
    const __nv_bfloat16* pbl = Bl + kb;
    #pragma unroll
    for (int c = 0; c < 8; c++) {
        const uint32_t so = sw128((uint32_t)(r * 128 + c * 16));
        cp16(sb + so,           pah + c * 8);
        cp16(sb + 16384 + so,   pal + c * 8);
        cp16(sb + 32768 + so,   pbh + c * 8);
        cp16(sb + 49152 + so,   pbl + c * 8);
    }
}
#endif

template <int EPI>
__global__ __launch_bounds__(128, 1)
void gemm_tc(const __nv_bfloat16* __restrict__ Ah, const __nv_bfloat16* __restrict__ Al,
             const __nv_bfloat16* __restrict__ Bh, const __nv_bfloat16* __restrict__ Bl,
             const float* __restrict__ bias, const float* __restrict__ resid,
             float* __restrict__ Cf,
             __nv_bfloat16* __restrict__ Chi, __nv_bfloat16* __restrict__ Clo,
             int N, int K)
{
#if HAS_TCGEN05
    extern __shared__ char smem[];
    const uint32_t sm = smem_u32_of(smem);
    const int tid = threadIdx.x;
    const int wid = tid >> 5;
    const int lid = tid & 31;
    const int m0 = blockIdx.y * 128;
    const int n0 = blockIdx.x * 128;
    const int T  = K >> 6;                 // K / 64

    if (tid == 0) {
        mbar_init(sm + 8,  1);
        mbar_init(sm + 16, 1);
        mbar_init(sm + 24, 1);
    }
    if (wid == 0) {
        TC_ALLOC(sm, 128);
        TC_RELINQ();
    }

    // prologue: stages 0..2
    stage_load(sm, 0, 0, Ah, Al, Bh, Bl, m0, n0, K, tid); CP_COMMIT();
    stage_load(sm, 1, 1, Ah, Al, Bh, Bl, m0, n0, K, tid); CP_COMMIT();
    stage_load(sm, 2, 2, Ah, Al, Bh, Bl, m0, n0, K, tid); CP_COMMIT();
    __syncthreads();

    uint32_t tmem;
    asm volatile("ld.shared.b32 %0, [%1];" : "=r"(tmem) : "r"(sm));

    for (int t = 0; t < T; ++t) {
        const int s = t % 3;
        if (t == T - 1) asm volatile("cp.async.wait_group 0;" ::: "memory");
        else            asm volatile("cp.async.wait_group 2;" ::: "memory");
        __syncthreads();
        FENCE_ASYNC();

        if (wid == 0 && elect_one()) {
            const uint32_t sb = sm + 1024 + s * STAGE_BYTES;
            const uint64_t dAh = smem_desc(sb);
            const uint64_t dAl = smem_desc(sb + 16384);
            const uint64_t dBh = smem_desc(sb + 32768);
            const uint64_t dBl = smem_desc(sb + 49152);
            #pragma unroll
            for (int ks = 0; ks < 4; ks++) {
                mma_f16_ss(tmem, dAh + ks*2, dBh + ks*2, GEMM_IDESC, !(t == 0 && ks == 0));
                mma_f16_ss(tmem, dAh + ks*2, dBl + ks*2, GEMM_IDESC, true);
                mma_f16_ss(tmem, dAl + ks*2, dBh + ks*2, GEMM_IDESC, true);
            }
            TC_COMMIT(sm + 8 + s * 8);
        }

        if (t + 3 < T) {
            mbar_wait(sm + 8 + s * 8, (uint32_t)((t / 3) & 1));
            stage_load(sm, s, t + 3, Ah, Al, Bh, Bl, m0, n0, K, tid);
        }
        CP_COMMIT();
    }

    // wait for all MMAs
    {
        const int s = (T - 1) % 3;
        mbar_wait(sm + 8 + s * 8, (uint32_t)(((T - 1) / 3) & 1));
    }
    TC_FENCE_AFTER();

    // epilogue: each warp reads its 32-lane TMEM subpartition; row = m0+wid*32+lid
    const int m = m0 + wid * 32 + lid;
    #pragma unroll
    for (int cb = 0; cb < 4; cb++) {
        uint32_t dr[32];
        TC_LD_X32(dr, tmem + cb * 32);
        TC_WAIT_LD();
        const int nb = n0 + cb * 32;
        if (EPI == EPI_GELU_SPLIT) {
            #pragma unroll
            for (int j = 0; j < 32; j += 4) {
                float4 v;
                v.x = gelu_tanh(__uint_as_float(dr[j])     + bias[nb + j]);
                v.y = gelu_tanh(__uint_as_float(dr[j + 1]) + bias[nb + j + 1]);
                v.z = gelu_tanh(__uint_as_float(dr[j + 2]) + bias[nb + j + 2]);
                v.w = gelu_tanh(__uint_as_float(dr[j + 3]) + bias[nb + j + 3]);
                split_store4(Chi, Clo, (size_t)m * N + nb + j, v);
            }
        } else {
            #pragma unroll
            for (int j = 0; j < 32; j += 4) {
                float4 v;
                v.x = __uint_as_float(dr[j])     + bias[nb + j];
                v.y = __uint_as_float(dr[j + 1]) + bias[nb + j + 1];
                v.z = __uint_as_float(dr[j + 2]) + bias[nb + j + 2];
                v.w = __uint_as_float(dr[j + 3]) + bias[nb + j + 3];
                if (EPI == EPI_BIAS_RES) {
                    const float4 rr = *(const float4*)(resid + (size_t)m * N + nb + j);
                    v.x += rr.x; v.y += rr.y; v.z += rr.z; v.w += rr.w;
                }
                *(float4*)(Cf + (size_t)m * N + nb + j) = v;
            }
        }
    }
    TC_FENCE_BEFORE();
    __syncthreads();
    if (wid == 0) TC_DEALLOC(tmem, 128);

#else  // ------------------- portable SIMT fallback ------------------------
    extern __shared__ char smem[];
    float* As = (float*)smem;                       // [16][128] k-major
    float* Bs = (float*)(smem + 16 * 128 * 4);      // [16][64]
    const int tid = threadIdx.x;
    const int m0 = blockIdx.y * 128;
    const int n0 = blockIdx.x * 128;
    const int ty = tid >> 3;   // 0..15
    const int tx = tid & 7;    // 0..7

    for (int nh = 0; nh < 2; nh++) {
        const int nb0 = n0 + nh * 64;
        float acc[8][8];
        #pragma unroll
        for (int i = 0; i < 8; i++)
            #pragma unroll
            for (int j = 0; j < 8; j++) acc[i][j] = 0.f;

        for (int k0 = 0; k0 < K; k0 += 16) {
            __syncthreads();
            #pragma unroll 4
            for (int i = tid; i < 2048; i += 128) {
                const int r = i >> 4, c = i & 15;
                const size_t gi = (size_t)(m0 + r) * K + k0 + c;
                As[c * 128 + r] = __bfloat162float(Ah[gi]) + __bfloat162float(Al[gi]);
            }
            #pragma unroll 2
            for (int i = tid; i < 1024; i += 128) {
                const int r = i >> 4, c = i & 15;
                const size_t gi = (size_t)(nb0 + r) * K + k0 + c;
                Bs[c * 64 + r] = __bfloat162float(Bh[gi]) + __bfloat162float(Bl[gi]);
            }
            __syncthreads();
            #pragma unroll
            for (int kk = 0; kk < 16; kk++) {
                float a[8], b[8];
                #pragma unroll
                for (int i = 0; i < 8; i++) a[i] = As[kk * 128 + ty * 8 + i];
                #pragma unroll
                for (int j = 0; j < 8; j++) b[j] = Bs[kk * 64 + tx * 8 + j];
                #pragma unroll
                for (int i = 0; i < 8; i++)
                    #pragma unroll
                    for (int j = 0; j < 8; j++)
                        acc[i][j] = fmaf(a[i], b[j], acc[i][j]);
            }
        }

        #pragma unroll
        for (int i = 0; i < 8; i++) {
            const int m = m0 + ty * 8 + i;
            #pragma unroll
            for (int j = 0; j < 8; j++) {
                const int n = nb0 + tx * 8 + j;
                float v = acc[i][j] + bias[n];
                if (EPI == EPI_GELU_SPLIT) {
                    v = gelu_tanh(v);
                    __nv_bfloat16 hv = __float2bfloat16(v);
                    Chi[(size_t)m * N + n] = hv;
                    Clo[(size_t)m * N + n] = __float2bfloat16(v - __bfloat162float(hv));
                } else {
                    if (EPI == EPI_BIAS_RES) v += resid[(size_t)m * N + n];
                    Cf[(size_t)m * N + n] = v;
                }
            }
        }
    }
#endif
}

// ---------------------------------------------------------------------------
// Causal flash attention, fp32 math; output written as bf16 (hi, lo) split.
// ---------------------------------------------------------------------------
__global__ __launch_bounds__(64)
void attn_kernel(const float* __restrict__ qkv,
                 __nv_bfloat16* __restrict__ out_hi,
                 __nv_bfloat16* __restrict__ out_lo)
{
    __shared__ float k_s[64][68];
    __shared__ float v_s[64][64];

    const int qt = blockIdx.x;
    const int bh = blockIdx.y;
    const int b  = bh >> 4;
    const int h  = bh & 15;
    const int t  = threadIdx.x;

    const size_t seq_base = (size_t)b * S_ * (3 * D_);
    const size_t head_off = (size_t)h * DH_;

    float q[64];
    {
        const float* qp = qkv + seq_base + head_off + (size_t)(qt * 64 + t) * (3 * D_);
        #pragma unroll
        for (int d = 0; d < 64; d += 4) {
            const float4 u = *(const float4*)(qp + d);
            q[d] = u.x; q[d+1] = u.y; q[d+2] = u.z; q[d+3] = u.w;
        }
    }

    float o[64];
    #pragma unroll
    for (int d = 0; d < 64; d++) o[d] = 0.f;
    float m = -1e30f, l = 0.f;

    for (int kt = 0; kt <= qt; kt++) {
        const float* kp = qkv + seq_base + D_     + head_off + (size_t)(kt * 64) * (3 * D_);
        const float* vp = qkv + seq_base + 2 * D_ + head_off + (size_t)(kt * 64) * (3 * D_);
        #pragma unroll 4
        for (int i = t; i < 64 * 16; i += 64) {
            const int r = i >> 4;
            const int c = (i & 15) << 2;
            const float4 kv = *(const float4*)(kp + (size_t)r * (3 * D_) + c);
            *(float4*)&k_s[r][c] = kv;
            const float4 vv = *(const float4*)(vp + (size_t)r * (3 * D_) + c);
            *(float4*)&v_s[r][c] = vv;
        }
        __syncthreads();

        const bool diag = (kt == qt);
        #pragma unroll
        for (int half = 0; half < 2; half++) {
            const int kbase = half * 32;
            float s[32];
            float mt = -1e30f;
            #pragma unroll 2
            for (int kc = 0; kc < 32; kc++) {
                const float4* krow = (const float4*)k_s[kbase + kc];
                float d0 = 0.f, d1 = 0.f, d2 = 0.f, d3 = 0.f;
                #pragma unroll
                for (int d4 = 0; d4 < 16; d4++) {
                    const float4 kv = krow[d4];
                    d0 = fmaf(q[4*d4+0], kv.x, d0);
                    d1 = fmaf(q[4*d4+1], kv.y, d1);
                    d2 = fmaf(q[4*d4+2], kv.z, d2);
                    d3 = fmaf(q[4*d4+3], kv.w, d3);
                }
                float sc = (d0 + d1 + d2 + d3) * 0.125f;
                if (diag && (kbase + kc) > t) sc = -1e30f;
                s[kc] = sc;
                mt = fmaxf(mt, sc);
            }
            const float m_new = fmaxf(m, mt);
            const float corr  = __expf(m - m_new);
            l *= corr;
            #pragma unroll
            for (int d = 0; d < 64; d++) o[d] *= corr;
            #pragma unroll 2
            for (int kc = 0; kc < 32; kc++) {
                const float p = __expf(s[kc] - m_new);
                l += p;
                const float4* vrow = (const float4*)v_s[kbase + kc];
                #pragma unroll
                for (int d4 = 0; d4 < 16; d4++) {
                    const float4 vv = vrow[d4];
                    o[4*d4+0] = fmaf(p, vv.x, o[4*d4+0]);
                    o[4*d4+1] = fmaf(p, vv.y, o[4*d4+1]);
                    o[4*d4+2] = fmaf(p, vv.z, o[4*d4+2]);
                    o[4*d4+3] = fmaf(p, vv.w, o[4*d4+3]);
                }
            }
            m = m_new;
        }
        __syncthreads();
    }

    const float inv_l = 1.0f / l;
    #pragma unroll
    for (int d4 = 0; d4 < 16; d4++) {
        float4 w;
        w.x = o[4*d4+0] * inv_l;
        w.y = o[4*d4+1] * inv_l;
        w.z = o[4*d4+2] * inv_l;
        w.w = o[4*d4+3] * inv_l;
        *(float4*)&k_s[t][4*d4] = w;
    }
    __syncthreads();
    const size_t out_base = ((size_t)b * S_ + qt * 64) * D_ + head_off;
    #pragma unroll 4
    for (int i = t; i < 64 * 16; i += 64) {
        const int r = i >> 4;
        const int c = (i & 15) << 2;
        float4 w;
        w.x = k_s[r][c]; w.y = k_s[r][c+1]; w.z = k_s[r][c+2]; w.w = k_s[r][c+3];
        split_store4(out_hi, out_lo, out_base + (size_t)r * D_ + c, w);
    }
}

// ---------------------------------------------------------------------------
// Launch
// ---------------------------------------------------------------------------
extern "C" void kernel_launch(void* const* d_in, const int* in_sizes, int n_in,
                              void* d_out, int out_size)
{
    const float* x     = (const float*)d_in[0];
    const float* ln1_g = (const float*)d_in[1];
    const float* ln1_b = (const float*)d_in[2];
    const float* w_qkv = (const float*)d_in[3];
    const float* b_qkv = (const float*)d_in[4];
    const float* w_o   = (const float*)d_in[5];
    const float* b_o   = (const float*)d_in[6];
    const float* ln2_g = (const float*)d_in[7];
    const float* ln2_b = (const float*)d_in[8];
    const float* w1    = (const float*)d_in[9];
    const float* b1    = (const float*)d_in[10];
    const float* w2    = (const float*)d_in[11];
    const float* b2    = (const float*)d_in[12];
    float* out = (float*)d_out;

    static bool inited = false;
    static float *p_qkv, *p_x2;
    static __nv_bfloat16 *p_act_h, *p_act_l, *p_big_h, *p_big_l;
    static __nv_bfloat16 *p_wqkv_h, *p_wqkv_l, *p_wo_h, *p_wo_l;
    static __nv_bfloat16 *p_w1_h, *p_w1_l, *p_w2_h, *p_w2_l;
    if (!inited) {
        void* p;
        cudaGetSymbolAddress(&p, g_qkv);    p_qkv    = (float*)p;
        cudaGetSymbolAddress(&p, g_x2);     p_x2     = (float*)p;
        cudaGetSymbolAddress(&p, g_act_hi); p_act_h  = (__nv_bfloat16*)p;
        cudaGetSymbolAddress(&p, g_act_lo); p_act_l  = (__nv_bfloat16*)p;
        cudaGetSymbolAddress(&p, g_big_hi); p_big_h  = (__nv_bfloat16*)p;
        cudaGetSymbolAddress(&p, g_big_lo); p_big_l  = (__nv_bfloat16*)p;
        cudaGetSymbolAddress(&p, g_wqkv_h); p_wqkv_h = (__nv_bfloat16*)p;
        cudaGetSymbolAddress(&p, g_wqkv_l); p_wqkv_l = (__nv_bfloat16*)p;
        cudaGetSymbolAddress(&p, g_wo_h);   p_wo_h   = (__nv_bfloat16*)p;
        cudaGetSymbolAddress(&p, g_wo_l);   p_wo_l   = (__nv_bfloat16*)p;
        cudaGetSymbolAddress(&p, g_w1_h);   p_w1_h   = (__nv_bfloat16*)p;
        cudaGetSymbolAddress(&p, g_w1_l);   p_w1_l   = (__nv_bfloat16*)p;
        cudaGetSymbolAddress(&p, g_w2_h);   p_w2_h   = (__nv_bfloat16*)p;
        cudaGetSymbolAddress(&p, g_w2_l);   p_w2_l   = (__nv_bfloat16*)p;
        cudaFuncSetAttribute(gemm_tc<EPI_BIAS>,       cudaFuncAttributeMaxDynamicSharedMemorySize, SMEM_GEMM);
        cudaFuncSetAttribute(gemm_tc<EPI_BIAS_RES>,   cudaFuncAttributeMaxDynamicSharedMemorySize, SMEM_GEMM);
        cudaFuncSetAttribute(gemm_tc<EPI_GELU_SPLIT>, cudaFuncAttributeMaxDynamicSharedMemorySize, SMEM_GEMM);
        inited = true;
    }

    // 0. weight splits (fp32 -> bf16 hi/lo)
    split_kernel<<<(3*D_*D_/4 + 255)/256, 256>>>(w_qkv, p_wqkv_h, p_wqkv_l, 3*D_*D_/4);
    split_kernel<<<(D_*D_/4   + 255)/256, 256>>>(w_o,   p_wo_h,   p_wo_l,   D_*D_/4);
    split_kernel<<<(FF_*D_/4  + 255)/256, 256>>>(w1,    p_w1_h,   p_w1_l,   FF_*D_/4);
    split_kernel<<<(D_*FF_/4  + 255)/256, 256>>>(w2,    p_w2_h,   p_w2_l,   D_*FF_/4);

    // 1. LN1 + split
    ln_split_kernel<<<TOK, 256>>>(x, ln1_g, ln1_b, p_act_h, p_act_l);

    // 2. QKV projection (fp32 out)
    gemm_tc<EPI_BIAS><<<dim3(3*D_/128, TOK/128), 128, SMEM_GEMM>>>(
        p_act_h, p_act_l, p_wqkv_h, p_wqkv_l, b_qkv, nullptr,
        p_qkv, nullptr, nullptr, 3*D_, D_);

    // 3. causal attention (fp32 math, bf16 split out)
    attn_kernel<<<dim3(S_/64, B_*H_), 64>>>(p_qkv, p_act_h, p_act_l);

    // 4. output projection + residual
    gemm_tc<EPI_BIAS_RES><<<dim3(D_/128, TOK/128), 128, SMEM_GEMM>>>(
        p_act_h, p_act_l, p_wo_h, p_wo_l, b_o, x,
        p_x2, nullptr, nullptr, D_, D_);

    // 5. LN2 + split
    ln_split_kernel<<<TOK, 256>>>(p_x2, ln2_g, ln2_b, p_act_h, p_act_l);

    // 6. FFN up + GELU + split (bf16 out)
    gemm_tc<EPI_GELU_SPLIT><<<dim3(FF_/128, TOK/128), 128, SMEM_GEMM>>>(
        p_act_h, p_act_l, p_w1_h, p_w1_l, b1, nullptr,
        nullptr, p_big_h, p_big_l, FF_, D_);

    // 7. FFN down + residual -> out
    gemm_tc<EPI_BIAS_RES><<<dim3(D_/128, TOK/128), 128, SMEM_GEMM>>>(
        p_big_h, p_big_l, p_w2_h, p_w2_l, b2, p_x2,
        out, nullptr, nullptr, D_, FF_);
}

// round 5
// speedup vs baseline: 1.9371x; 1.0401x over previous
#include <cuda_runtime.h>
#include <cuda_bf16.h>
#include <math.h>
#include <stdint.h>

// ---------------------------------------------------------------------------
// Per-compilation-pass feature detection (plain compute_103 pass gets fallback)
// ---------------------------------------------------------------------------
#if defined(__CUDA_ARCH__)
# if defined(__CUDA_ARCH_FEAT_SM103_ALL) || defined(__CUDA_ARCH_FEAT_SM100_ALL) || \
     (defined(__CUDA_ARCH_FAMILY_SPECIFIC__) && (__CUDA_ARCH_FAMILY_SPECIFIC__ >= 1000))
#  define HAS_TCGEN05 1
# else
#  define HAS_TCGEN05 0
# endif
#else
# define HAS_TCGEN05 0
#endif

// ---------------------------------------------------------------------------
// Problem constants
// ---------------------------------------------------------------------------
#define B_    8
#define S_    1024
#define D_    1024
#define H_    16
#define DH_   64
#define FF_   4096
#define TOK   (B_ * S_)

// ---------------------------------------------------------------------------
// Scratch
// ---------------------------------------------------------------------------
__device__ float g_qkv[(size_t)TOK * 3 * D_];
__device__ float g_x2 [(size_t)TOK * D_];
__device__ __nv_bfloat16 g_act_hi[(size_t)TOK * D_];
__device__ __nv_bfloat16 g_act_lo[(size_t)TOK * D_];
__device__ __nv_bfloat16 g_big_hi[(size_t)TOK * FF_];
__device__ __nv_bfloat16 g_big_lo[(size_t)TOK * FF_];
__device__ __nv_bfloat16 g_wqkv_h[(size_t)3 * D_ * D_];
__device__ __nv_bfloat16 g_wqkv_l[(size_t)3 * D_ * D_];
__device__ __nv_bfloat16 g_wo_h[(size_t)D_ * D_];
__device__ __nv_bfloat16 g_wo_l[(size_t)D_ * D_];
__device__ __nv_bfloat16 g_w1_h[(size_t)FF_ * D_];
__device__ __nv_bfloat16 g_w1_l[(size_t)FF_ * D_];
__device__ __nv_bfloat16 g_w2_h[(size_t)D_ * FF_];
__device__ __nv_bfloat16 g_w2_l[(size_t)D_ * FF_];

// ---------------------------------------------------------------------------
// PTX helpers
// ---------------------------------------------------------------------------
#if HAS_TCGEN05
__device__ __forceinline__ uint32_t smem_u32_of(const void* p) {
    uint32_t a;
    asm("{ .reg .u64 t; cvta.to.shared.u64 t, %1; cvt.u32.u64 %0, t; }" : "=r"(a) : "l"(p));
    return a;
}
__device__ __forceinline__ void cp16(uint32_t dst, const void* src) {
    asm volatile("cp.async.cg.shared.global [%0], [%1], 16;" :: "r"(dst), "l"(src));
}
__device__ __forceinline__ uint32_t sw128(uint32_t off) { return off ^ ((off >> 3) & 0x70); }

__device__ __forceinline__ uint64_t smem_desc(uint32_t addr) {
    constexpr uint64_t BASE = (uint64_t(2) << 61)   // SW128
                            | (uint64_t(1) << 46)   // Blackwell
                            | (uint64_t(64) << 32)  // SBO = 64
                            | (uint64_t(1) << 16);  // LBO = 1
    return BASE | ((uint64_t)(addr >> 4) & 0x3FFF);
}
// idesc: kind::f16, d=f32, a=bf16, b=bf16, M=128, N=128
#define GEMM_IDESC ((1u<<4) | (1u<<7) | (1u<<10) | ((128u/8)<<17) | ((128u/16)<<24))

__device__ __forceinline__ void mma_f16_ss(uint32_t d, uint64_t a, uint64_t b,
                                           uint32_t idesc, bool acc) {
    uint32_t e = acc ? 1u : 0u;
    asm volatile(
        "{\n\t.reg .pred p;\n\t"
        "setp.ne.u32 p, %4, 0;\n\t"
        "tcgen05.mma.cta_group::1.kind::f16 [%0], %1, %2, %3, {%5, %5, %5, %5}, p;\n\t}"
        :: "r"(d), "l"(a), "l"(b), "r"(idesc), "r"(e), "r"(0u) : "memory");
}
__device__ __forceinline__ void mbar_init(uint32_t addr, uint32_t cnt) {
    asm volatile("mbarrier.init.shared.b64 [%0], %1;" :: "r"(addr), "r"(cnt) : "memory");
}
__device__ __forceinline__ void mbar_arrive(uint32_t addr) {
    asm volatile("mbarrier.arrive.shared.b64 _, [%0];" :: "r"(addr) : "memory");
}
__device__ __forceinline__ void mbar_wait(uint32_t addr, uint32_t parity) {
    asm volatile(
        "{\n\t.reg .pred P;\n\t"
        "W%=:\n\t"
        "mbarrier.try_wait.parity.acquire.cta.shared::cta.b64 P, [%0], %1, 0x989680;\n\t"
        "@!P bra W%=;\n\t}"
        :: "r"(addr), "r"(parity) : "memory");
}

#define TC_ALLOC(sm, n)   asm volatile("tcgen05.alloc.cta_group::1.sync.aligned.shared::cta.b32 [%0], %1;" :: "r"(sm), "r"(n) : "memory")
#define TC_RELINQ()       asm volatile("tcgen05.relinquish_alloc_permit.cta_group::1.sync.aligned;")
#define TC_DEALLOC(t, n)  asm volatile("tcgen05.dealloc.cta_group::1.sync.aligned.b32 %0, %1;" :: "r"(t), "r"(n))
#define TC_COMMIT(mb)     asm volatile("tcgen05.commit.cta_group::1.mbarrier::arrive::one.shared::cluster.b64 [%0];" :: "r"(mb) : "memory")
#define TC_FENCE_AFTER()  asm volatile("tcgen05.fence::after_thread_sync;" ::: "memory")
#define TC_FENCE_BEFORE() asm volatile("tcgen05.fence::before_thread_sync;" ::: "memory")
#define TC_WAIT_LD()      asm volatile("tcgen05.wait::ld.sync.aligned;" ::: "memory")
#define CP_COMMIT()       asm volatile("cp.async.commit_group;" ::: "memory")
#define FENCE_ASYNC()     asm volatile("fence.proxy.async.shared::cta;" ::: "memory")

#define TC_LD_X32(r, t) \
    asm volatile( \
        "tcgen05.ld.sync.aligned.32x32b.x32.b32 " \
        "{%0, %1, %2, %3, %4, %5, %6, %7, " \
        " %8, %9, %10, %11, %12, %13, %14, %15, " \
        " %16, %17, %18, %19, %20, %21, %22, %23, " \
        " %24, %25, %26, %27, %28, %29, %30, %31}, [%32];" \
        : "=r"((r)[0]),  "=r"((r)[1]),  "=r"((r)[2]),  "=r"((r)[3]), \
          "=r"((r)[4]),  "=r"((r)[5]),  "=r"((r)[6]),  "=r"((r)[7]), \
          "=r"((r)[8]),  "=r"((r)[9]),  "=r"((r)[10]), "=r"((r)[11]), \
          "=r"((r)[12]), "=r"((r)[13]), "=r"((r)[14]), "=r"((r)[15]), \
          "=r"((r)[16]), "=r"((r)[17]), "=r"((r)[18]), "=r"((r)[19]), \
          "=r"((r)[20]), "=r"((r)[21]), "=r"((r)[22]), "=r"((r)[23]), \
          "=r"((r)[24]), "=r"((r)[25]), "=r"((r)[26]), "=r"((r)[27]), \
          "=r"((r)[28]), "=r"((r)[29]), "=r"((r)[30]), "=r"((r)[31]) \
        : "r"(t))
#endif  // HAS_TCGEN05

// ---------------------------------------------------------------------------
// fp32 -> bf16 (hi, lo) split helpers
// ---------------------------------------------------------------------------
__device__ __forceinline__ void split_store4(__nv_bfloat16* __restrict__ hi,
                                             __nv_bfloat16* __restrict__ lo,
                                             size_t idx, float4 v) {
    __nv_bfloat16 h0 = __float2bfloat16(v.x);
    __nv_bfloat16 h1 = __float2bfloat16(v.y);
    __nv_bfloat16 h2 = __float2bfloat16(v.z);
    __nv_bfloat16 h3 = __float2bfloat16(v.w);
    __nv_bfloat16 l0 = __float2bfloat16(v.x - __bfloat162float(h0));
    __nv_bfloat16 l1 = __float2bfloat16(v.y - __bfloat162float(h1));
    __nv_bfloat16 l2 = __float2bfloat16(v.z - __bfloat162float(h2));
    __nv_bfloat16 l3 = __float2bfloat16(v.w - __bfloat162float(h3));
    __nv_bfloat162 ha; ha.x = h0; ha.y = h1;
    __nv_bfloat162 hb; hb.x = h2; hb.y = h3;
    __nv_bfloat162 la; la.x = l0; la.y = l1;
    __nv_bfloat162 lb; lb.x = l2; lb.y = l3;
    *(__nv_bfloat162*)(hi + idx)     = ha;
    *(__nv_bfloat162*)(hi + idx + 2) = hb;
    *(__nv_bfloat162*)(lo + idx)     = la;
    *(__nv_bfloat162*)(lo + idx + 2) = lb;
}

__global__ __launch_bounds__(256)
void split_kernel(const float* __restrict__ x,
                  __nv_bfloat16* __restrict__ hi,
                  __nv_bfloat16* __restrict__ lo, int n4)
{
    int i = blockIdx.x * 256 + threadIdx.x;
    if (i < n4) {
        float4 v = ((const float4*)x)[i];
        split_store4(hi, lo, (size_t)i * 4, v);
    }
}

// ---------------------------------------------------------------------------
// LayerNorm fused with bf16 split output
// ---------------------------------------------------------------------------
__global__ __launch_bounds__(256)
void ln_split_kernel(const float* __restrict__ x,
                     const float* __restrict__ gw,
                     const float* __restrict__ bw,
                     __nv_bfloat16* __restrict__ out_hi,
                     __nv_bfloat16* __restrict__ out_lo)
{
    __shared__ float red[16];
    const int row = blockIdx.x;
    const int tid = threadIdx.x;

    const float4 v = ((const float4*)(x + (size_t)row * D_))[tid];
    float s  = v.x + v.y + v.z + v.w;
    float ss = v.x*v.x + v.y*v.y + v.z*v.z + v.w*v.w;

    #pragma unroll
    for (int o = 16; o; o >>= 1) {
        s  += __shfl_xor_sync(0xffffffffu, s,  o);
        ss += __shfl_xor_sync(0xffffffffu, ss, o);
    }
    const int wid = tid >> 5, lid = tid & 31;
    if (lid == 0) { red[wid] = s; red[8 + wid] = ss; }
    __syncthreads();

    float sum = 0.f, sq = 0.f;
    #pragma unroll
    for (int i = 0; i < 8; i++) { sum += red[i]; sq += red[8 + i]; }

    const float mu  = sum * (1.0f / D_);
    const float var = sq  * (1.0f / D_) - mu * mu;
    const float rs  = rsqrtf(var + 1e-5f);

    const float4 g4 = ((const float4*)gw)[tid];
    const float4 b4 = ((const float4*)bw)[tid];
    float4 o;
    o.x = (v.x - mu) * rs * g4.x + b4.x;
    o.y = (v.y - mu) * rs * g4.y + b4.y;
    o.z = (v.z - mu) * rs * g4.z + b4.z;
    o.w = (v.w - mu) * rs * g4.w + b4.w;
    split_store4(out_hi, out_lo, (size_t)row * D_ + tid * 4, o);
}

// ---------------------------------------------------------------------------
// GEMM (TN), warp-specialized tcgen05 path.
//   - 256 threads. Warps 4-7: cp.async producers. Thread 0: MMA issuer.
//   - 3 stages x 64KB (BK=64). full[s]: 128 producer arrivals; done[s]: commit
//     (stage recycling only — in-order waits, no parity aliasing).
//   - fin barrier: ONE commit after all MMAs; single phase, all threads wait
//     parity 0 before the epilogue (fixes the round-4 aliasing race).
//   - Epilogue split across all 8 warps.
// ---------------------------------------------------------------------------
enum { EPI_BIAS = 0, EPI_BIAS_RES = 1, EPI_GELU_SPLIT = 2 };

__device__ __forceinline__ float gelu_tanh(float x)
{
    const float u = 0.7978845608028654f * (x + 0.044715f * x * x * x);
    return 0.5f * x * (1.0f + tanhf(u));
}

#define STAGE_BYTES 65536
#define SMEM_GEMM   (1024 + 3 * STAGE_BYTES)

#if HAS_TCGEN05
__device__ __forceinline__ void stage_load(uint32_t smem_base, int s, int kt,
                                           const __nv_bfloat16* __restrict__ Ah,
                                           const __nv_bfloat16* __restrict__ Al,
                                           const __nv_bfloat16* __restrict__ Bh,
                                           const __nv_bfloat16* __restrict__ Bl,
                                           int m0, int n0, int K, int ptid)
{
    const uint32_t sb = smem_base + 1024 + s * STAGE_BYTES;
    const int r = ptid;                         // 0..127
    const size_t ka = (size_t)(m0 + r) * K + (size_t)kt * 64;
    const size_t kb = (size_t)(n0 + r) * K + (size_t)kt * 64;
    const __nv_bfloat16* pah = Ah + ka;
    const __nv_bfloat16* pal = Al + ka;
    const __nv_bfloat16* pbh = Bh + kb;
    const __nv_bfloat16* pbl = Bl + kb;
    #pragma unroll
    for (int c = 0; c < 8; c++) {
        const uint32_t so = sw128((uint32_t)(r * 128 + c * 16));
        cp16(sb + so,           pah + c * 8);
        cp16(sb + 16384 + so,   pal + c * 8);
        cp16(sb + 32768 + so,   pbh + c * 8);
        cp16(sb + 49152 + so,   pbl + c * 8);
    }
}
#endif

template <int EPI>
__global__ __launch_bounds__(256, 1)
void gemm_tc(const __nv_bfloat16* __restrict__ Ah, const __nv_bfloat16* __restrict__ Al,
             const __nv_bfloat16* __restrict__ Bh, const __nv_bfloat16* __restrict__ Bl,
             const float* __restrict__ bias, const float* __restrict__ resid,
             float* __restrict__ Cf,
             __nv_bfloat16* __restrict__ Chi, __nv_bfloat16* __restrict__ Clo,
             int N, int K)
{
#if HAS_TCGEN05
    extern __shared__ char smem[];
    const uint32_t sm = smem_u32_of(smem);
    const int tid = threadIdx.x;
    const int wid = tid >> 5;
    const int lid = tid & 31;
    const int m0 = blockIdx.y * 128;
    const int n0 = blockIdx.x * 128;
    const int T  = K >> 6;                 // K / 64

    // barriers: done[s] at sm+8+8s (count 1, stage recycling);
    //           full[s] at sm+32+8s (count 128, producer arrivals);
    //           fin     at sm+56    (count 1, single-phase final completion)
    if (tid == 0) {
        mbar_init(sm + 8,  1);   mbar_init(sm + 16, 1);   mbar_init(sm + 24, 1);
        mbar_init(sm + 32, 128); mbar_init(sm + 40, 128); mbar_init(sm + 48, 128);
        mbar_init(sm + 56, 1);
    }
    if (wid == 0) {
        TC_ALLOC(sm, 128);
        TC_RELINQ();
    }
    __syncthreads();

    uint32_t tmem;
    asm volatile("ld.shared.b32 %0, [%1];" : "=r"(tmem) : "r"(sm));

    if (wid >= 4) {
        // ------------------------- producers -------------------------------
        const int ptid = tid - 128;
        for (int t = 0; t < T; ++t) {
            const int s = t % 3;
            if (t >= 3) mbar_wait(sm + 8 + s * 8, ((t / 3) - 1) & 1);
            stage_load(sm, s, t, Ah, Al, Bh, Bl, m0, n0, K, ptid);
            CP_COMMIT();
            if (t >= 1) {
                asm volatile("cp.async.wait_group 1;" ::: "memory");
                FENCE_ASYNC();
                mbar_arrive(sm + 32 + ((t - 1) % 3) * 8);
            }
        }
        asm volatile("cp.async.wait_group 0;" ::: "memory");
        FENCE_ASYNC();
        mbar_arrive(sm + 32 + ((T - 1) % 3) * 8);
    } else if (tid == 0) {
        // ------------------------- MMA issuer ------------------------------
        uint64_t dAh[3], dAl[3], dBh[3], dBl[3];
        #pragma unroll
        for (int s = 0; s < 3; s++) {
            const uint32_t sb = sm + 1024 + s * STAGE_BYTES;
            dAh[s] = smem_desc(sb);
            dAl[s] = smem_desc(sb + 16384);
            dBh[s] = smem_desc(sb + 32768);
            dBl[s] = smem_desc(sb + 49152);
        }
        for (int t = 0; t < T; ++t) {
            const int s = t % 3;
            mbar_wait(sm + 32 + s * 8, (t / 3) & 1);
            FENCE_ASYNC();
            #pragma unroll
            for (int ks = 0; ks < 4; ks++) {
                mma_f16_ss(tmem, dAh[s] + ks*2, dBh[s] + ks*2, GEMM_IDESC, !(t == 0 && ks == 0));
                mma_f16_ss(tmem, dAh[s] + ks*2, dBl[s] + ks*2, GEMM_IDESC, true);
                mma_f16_ss(tmem, dAl[s] + ks*2, dBh[s] + ks*2, GEMM_IDESC, true);
            }
            TC_COMMIT(sm + 8 + s * 8);
        }
        // single-phase completion signal: tracks ALL MMAs issued by this thread
        TC_COMMIT(sm + 56);
    }

    // ALL threads wait the single-phase fin barrier (no parity aliasing)
    mbar_wait(sm + 56, 0);
    TC_FENCE_AFTER();

    // epilogue: 8 warps; warp w -> rows (w&3)*32, column blocks (w>>2)*2 + {0,1}
    const int m = m0 + (wid & 3) * 32 + lid;
    const int cb0 = (wid >> 2) * 2;
    #pragma unroll
    for (int cc = 0; cc < 2; cc++) {
        const int cb = cb0 + cc;
        uint32_t dr[32];
        TC_LD_X32(dr, tmem + cb * 32);
        TC_WAIT_LD();
        const int nb = n0 + cb * 32;
        if (EPI == EPI_GELU_SPLIT) {
            #pragma unroll
            for (int j = 0; j < 32; j += 4) {
                float4 v;
                v.x = gelu_tanh(__uint_as_float(dr[j])     + bias[nb + j]);
                v.y = gelu_tanh(__uint_as_float(dr[j + 1]) + bias[nb + j + 1]);
                v.z = gelu_tanh(__uint_as_float(dr[j + 2]) + bias[nb + j + 2]);
                v.w = gelu_tanh(__uint_as_float(dr[j + 3]) + bias[nb + j + 3]);
                split_store4(Chi, Clo, (size_t)m * N + nb + j, v);
            }
        } else {
            #pragma unroll
            for (int j = 0; j < 32; j += 4) {
                float4 v;
                v.x = __uint_as_float(dr[j])     + bias[nb + j];
                v.y = __uint_as_float(dr[j + 1]) + bias[nb + j + 1];
                v.z = __uint_as_float(dr[j + 2]) + bias[nb + j + 2];
                v.w = __uint_as_float(dr[j + 3]) + bias[nb + j + 3];
                if (EPI == EPI_BIAS_RES) {
                    const float4 rr = *(const float4*)(resid + (size_t)m * N + nb + j);
                    v.x += rr.x; v.y += rr.y; v.z += rr.z; v.w += rr.w;
                }
                *(float4*)(Cf + (size_t)m * N + nb + j) = v;
            }
        }
    }
    TC_FENCE_BEFORE();
    __syncthreads();
    if (wid == 0) TC_DEALLOC(tmem, 128);

#else  // ------------------- portable SIMT fallback (256 threads) ----------
    extern __shared__ char smem[];
    float* As = (float*)smem;                       // [16][128] k-major
    float* Bs = (float*)(smem + 16 * 128 * 4);      // [16][128]
    const int tid = threadIdx.x;
    const int m0 = blockIdx.y * 128;
    const int n0 = blockIdx.x * 128;
    const int ty = tid >> 4;   // 0..15
    const int tx = tid & 15;   // 0..15

    float acc[8][8];
    #pragma unroll
    for (int i = 0; i < 8; i++)
        #pragma unroll
        for (int j = 0; j < 8; j++) acc[i][j] = 0.f;

    for (int k0 = 0; k0 < K; k0 += 16) {
        __syncthreads();
        #pragma unroll 4
        for (int i = tid; i < 2048; i += 256) {
            const int r = i >> 4, c = i & 15;
            const size_t gia = (size_t)(m0 + r) * K + k0 + c;
            As[c * 128 + r] = __bfloat162float(Ah[gia]) + __bfloat162float(Al[gia]);
            const size_t gib = (size_t)(n0 + r) * K + k0 + c;
            Bs[c * 128 + r] = __bfloat162float(Bh[gib]) + __bfloat162float(Bl[gib]);
        }
        __syncthreads();
        #pragma unroll
        for (int kk = 0; kk < 16; kk++) {
            float a[8], b[8];
            #pragma unroll
            for (int i = 0; i < 8; i++) a[i] = As[kk * 128 + ty * 8 + i];
            #pragma unroll
            for (int j = 0; j < 8; j++) b[j] = Bs[kk * 128 + tx * 8 + j];
            #pragma unroll
            for (int i = 0; i < 8; i++)
                #pragma unroll
                for (int j = 0; j < 8; j++)
                    acc[i][j] = fmaf(a[i], b[j], acc[i][j]);
        }
    }

    #pragma unroll
    for (int i = 0; i < 8; i++) {
        const int m = m0 + ty * 8 + i;
        #pragma unroll
        for (int j = 0; j < 8; j++) {
            const int n = n0 + tx * 8 + j;
            float v = acc[i][j] + bias[n];
            if (EPI == EPI_GELU_SPLIT) {
                v = gelu_tanh(v);
                __nv_bfloat16 hv = __float2bfloat16(v);
                Chi[(size_t)m * N + n] = hv;
                Clo[(size_t)m * N + n] = __float2bfloat16(v - __bfloat162float(hv));
            } else {
                if (EPI == EPI_BIAS_RES) v += resid[(size_t)m * N + n];
                Cf[(size_t)m * N + n] = v;
            }
        }
    }
#endif
}

// ---------------------------------------------------------------------------
// Causal flash attention, fp32 math; output written as bf16 (hi, lo) split.
// ---------------------------------------------------------------------------
__global__ __launch_bounds__(64)
void attn_kernel(const float* __restrict__ qkv,
                 __nv_bfloat16* __restrict__ out_hi,
                 __nv_bfloat16* __restrict__ out_lo)
{
    __shared__ float k_s[64][68];
    __shared__ float v_s[64][64];

    const int qt = blockIdx.x;
    const int bh = blockIdx.y;
    const int b  = bh >> 4;
    const int h  = bh & 15;
    const int t  = threadIdx.x;

    const size_t seq_base = (size_t)b * S_ * (3 * D_);
    const size_t head_off = (size_t)h * DH_;

    float q[64];
    {
        const float* qp = qkv + seq_base + head_off + (size_t)(qt * 64 + t) * (3 * D_);
        #pragma unroll
        for (int d = 0; d < 64; d += 4) {
            const float4 u = *(const float4*)(qp + d);
            q[d] = u.x; q[d+1] = u.y; q[d+2] = u.z; q[d+3] = u.w;
        }
    }

    float o[64];
    #pragma unroll
    for (int d = 0; d < 64; d++) o[d] = 0.f;
    float m = -1e30f, l = 0.f;

    for (int kt = 0; kt <= qt; kt++) {
        const float* kp = qkv + seq_base + D_     + head_off + (size_t)(kt * 64) * (3 * D_);
        const float* vp = qkv + seq_base + 2 * D_ + head_off + (size_t)(kt * 64) * (3 * D_);
        #pragma unroll 4
        for (int i = t; i < 64 * 16; i += 64) {
            const int r = i >> 4;
            const int c = (i & 15) << 2;
            const float4 kv = *(const float4*)(kp + (size_t)r * (3 * D_) + c);
            *(float4*)&k_s[r][c] = kv;
            const float4 vv = *(const float4*)(vp + (size_t)r * (3 * D_) + c);
            *(float4*)&v_s[r][c] = vv;
        }
        __syncthreads();

        const bool diag = (kt == qt);
        #pragma unroll
        for (int half = 0; half < 2; half++) {
            const int kbase = half * 32;
            float s[32];
            float mt = -1e30f;
            #pragma unroll 2
            for (int kc = 0; kc < 32; kc++) {
                const float4* krow = (const float4*)k_s[kbase + kc];
                float d0 = 0.f, d1 = 0.f, d2 = 0.f, d3 = 0.f;
                #pragma unroll
                for (int d4 = 0; d4 < 16; d4++) {
                    const float4 kv = krow[d4];
                    d0 = fmaf(q[4*d4+0], kv.x, d0);
                    d1 = fmaf(q[4*d4+1], kv.y, d1);
                    d2 = fmaf(q[4*d4+2], kv.z, d2);
                    d3 = fmaf(q[4*d4+3], kv.w, d3);
                }
                float sc = (d0 + d1 + d2 + d3) * 0.125f;
                if (diag && (kbase + kc) > t) sc = -1e30f;
                s[kc] = sc;
                mt = fmaxf(mt, sc);
            }
            const float m_new = fmaxf(m, mt);
            const float corr  = __expf(m - m_new);
            l *= corr;
            #pragma unroll
            for (int d = 0; d < 64; d++) o[d] *= corr;
            #pragma unroll 2
            for (int kc = 0; kc < 32; kc++) {
                const float p = __expf(s[kc] - m_new);
                l += p;
                const float4* vrow = (const float4*)v_s[kbase + kc];
                #pragma unroll
                for (int d4 = 0; d4 < 16; d4++) {
                    const float4 vv = vrow[d4];
                    o[4*d4+0] = fmaf(p, vv.x, o[4*d4+0]);
                    o[4*d4+1] = fmaf(p, vv.y, o[4*d4+1]);
                    o[4*d4+2] = fmaf(p, vv.z, o[4*d4+2]);
                    o[4*d4+3] = fmaf(p, vv.w, o[4*d4+3]);
                }
            }
            m = m_new;
        }
        __syncthreads();
    }

    const float inv_l = 1.0f / l;
    #pragma unroll
    for (int d4 = 0; d4 < 16; d4++) {
        float4 w;
        w.x = o[4*d4+0] * inv_l;
        w.y = o[4*d4+1] * inv_l;
        w.z = o[4*d4+2] * inv_l;
        w.w = o[4*d4+3] * inv_l;
        *(float4*)&k_s[t][4*d4] = w;
    }
    __syncthreads();
    const size_t out_base = ((size_t)b * S_ + qt * 64) * D_ + head_off;
    #pragma unroll 4
    for (int i = t; i < 64 * 16; i += 64) {
        const int r = i >> 4;
        const int c = (i & 15) << 2;
        float4 w;
        w.x = k_s[r][c]; w.y = k_s[r][c+1]; w.z = k_s[r][c+2]; w.w = k_s[r][c+3];
        split_store4(out_hi, out_lo, out_base + (size_t)r * D_ + c, w);
    }
}

// ---------------------------------------------------------------------------
// Launch
// ---------------------------------------------------------------------------
extern "C" void kernel_launch(void* const* d_in, const int* in_sizes, int n_in,
                              void* d_out, int out_size)
{
    const float* x     = (const float*)d_in[0];
    const float* ln1_g = (const float*)d_in[1];
    const float* ln1_b = (const float*)d_in[2];
    const float* w_qkv = (const float*)d_in[3];
    const float* b_qkv = (const float*)d_in[4];
    const float* w_o   = (const float*)d_in[5];
    const float* b_o   = (const float*)d_in[6];
    const float* ln2_g = (const float*)d_in[7];
    const float* ln2_b = (const float*)d_in[8];
    const float* w1    = (const float*)d_in[9];
    const float* b1    = (const float*)d_in[10];
    const float* w2    = (const float*)d_in[11];
    const float* b2    = (const float*)d_in[12];
    float* out = (float*)d_out;

    static bool inited = false;
    static float *p_qkv, *p_x2;
    static __nv_bfloat16 *p_act_h, *p_act_l, *p_big_h, *p_big_l;
    static __nv_bfloat16 *p_wqkv_h, *p_wqkv_l, *p_wo_h, *p_wo_l;
    static __nv_bfloat16 *p_w1_h, *p_w1_l, *p_w2_h, *p_w2_l;
    if (!inited) {
        void* p;
        cudaGetSymbolAddress(&p, g_qkv);    p_qkv    = (float*)p;
        cudaGetSymbolAddress(&p, g_x2);     p_x2     = (float*)p;
        cudaGetSymbolAddress(&p, g_act_hi); p_act_h  = (__nv_bfloat16*)p;
        cudaGetSymbolAddress(&p, g_act_lo); p_act_l  = (__nv_bfloat16*)p;
        cudaGetSymbolAddress(&p, g_big_hi); p_big_h  = (__nv_bfloat16*)p;
        cudaGetSymbolAddress(&p, g_big_lo); p_big_l  = (__nv_bfloat16*)p;
        cudaGetSymbolAddress(&p, g_wqkv_h); p_wqkv_h = (__nv_bfloat16*)p;
        cudaGetSymbolAddress(&p, g_wqkv_l); p_wqkv_l = (__nv_bfloat16*)p;
        cudaGetSymbolAddress(&p, g_wo_h);   p_wo_h   = (__nv_bfloat16*)p;
        cudaGetSymbolAddress(&p, g_wo_l);   p_wo_l   = (__nv_bfloat16*)p;
        cudaGetSymbolAddress(&p, g_w1_h);   p_w1_h   = (__nv_bfloat16*)p;
        cudaGetSymbolAddress(&p, g_w1_l);   p_w1_l   = (__nv_bfloat16*)p;
        cudaGetSymbolAddress(&p, g_w2_h);   p_w2_h   = (__nv_bfloat16*)p;
        cudaGetSymbolAddress(&p, g_w2_l);   p_w2_l   = (__nv_bfloat16*)p;
        cudaFuncSetAttribute(gemm_tc<EPI_BIAS>,       cudaFuncAttributeMaxDynamicSharedMemorySize, SMEM_GEMM);
        cudaFuncSetAttribute(gemm_tc<EPI_BIAS_RES>,   cudaFuncAttributeMaxDynamicSharedMemorySize, SMEM_GEMM);
        cudaFuncSetAttribute(gemm_tc<EPI_GELU_SPLIT>, cudaFuncAttributeMaxDynamicSharedMemorySize, SMEM_GEMM);
        inited = true;
    }

    // 0. weight splits
    split_kernel<<<(3*D_*D_/4 + 255)/256, 256>>>(w_qkv, p_wqkv_h, p_wqkv_l, 3*D_*D_/4);
    split_kernel<<<(D_*D_/4   + 255)/256, 256>>>(w_o,   p_wo_h,   p_wo_l,   D_*D_/4);
    split_kernel<<<(FF_*D_/4  + 255)/256, 256>>>(w1,    p_w1_h,   p_w1_l,   FF_*D_/4);
    split_kernel<<<(D_*FF_/4  + 255)/256, 256>>>(w2,    p_w2_h,   p_w2_l,   D_*FF_/4);

    // 1. LN1 + split
    ln_split_kernel<<<TOK, 256>>>(x, ln1_g, ln1_b, p_act_h, p_act_l);

    // 2. QKV projection
    gemm_tc<EPI_BIAS><<<dim3(3*D_/128, TOK/128), 256, SMEM_GEMM>>>(
        p_act_h, p_act_l, p_wqkv_h, p_wqkv_l, b_qkv, nullptr,
        p_qkv, nullptr, nullptr, 3*D_, D_);

    // 3. causal attention
    attn_kernel<<<dim3(S_/64, B_*H_), 64>>>(p_qkv, p_act_h, p_act_l);

    // 4. output projection + residual
    gemm_tc<EPI_BIAS_RES><<<dim3(D_/128, TOK/128), 256, SMEM_GEMM>>>(
        p_act_h, p_act_l, p_wo_h, p_wo_l, b_o, x,
        p_x2, nullptr, nullptr, D_, D_);

    // 5. LN2 + split
    ln_split_kernel<<<TOK, 256>>>(p_x2, ln2_g, ln2_b, p_act_h, p_act_l);

    // 6. FFN up + GELU + split
    gemm_tc<EPI_GELU_SPLIT><<<dim3(FF_/128, TOK/128), 256, SMEM_GEMM>>>(
        p_act_h, p_act_l, p_w1_h, p_w1_l, b1, nullptr,
        nullptr, p_big_h, p_big_l, FF_, D_);

    // 7. FFN down + residual -> out
    gemm_tc<EPI_BIAS_RES><<<dim3(D_/128, TOK/128), 256, SMEM_GEMM>>>(
        p_big_h, p_big_l, p_w2_h, p_w2_l, b2, p_x2,
        out, nullptr, nullptr, D_, FF_);
}

// round 6
// speedup vs baseline: 2.3139x; 1.1945x over previous
#include <cuda_runtime.h>
#include <cuda_bf16.h>
#include <math.h>
#include <stdint.h>

// ---------------------------------------------------------------------------
// Per-compilation-pass feature detection (plain compute_103 pass gets fallback)
// ---------------------------------------------------------------------------
#if defined(__CUDA_ARCH__)
# if defined(__CUDA_ARCH_FEAT_SM103_ALL) || defined(__CUDA_ARCH_FEAT_SM100_ALL) || \
     (defined(__CUDA_ARCH_FAMILY_SPECIFIC__) && (__CUDA_ARCH_FAMILY_SPECIFIC__ >= 1000))
#  define HAS_TCGEN05 1
# else
#  define HAS_TCGEN05 0
# endif
#else
# define HAS_TCGEN05 0
#endif

// ---------------------------------------------------------------------------
// Problem constants
// ---------------------------------------------------------------------------
#define B_    8
#define S_    1024
#define D_    1024
#define H_    16
#define DH_   64
#define FF_   4096
#define TOK   (B_ * S_)

// ---------------------------------------------------------------------------
// Scratch
// ---------------------------------------------------------------------------
__device__ float g_qkv[(size_t)TOK * 3 * D_];
__device__ float g_x2 [(size_t)TOK * D_];
__device__ __nv_bfloat16 g_act_hi[(size_t)TOK * D_];
__device__ __nv_bfloat16 g_act_lo[(size_t)TOK * D_];
__device__ __nv_bfloat16 g_big_hi[(size_t)TOK * FF_];
__device__ __nv_bfloat16 g_big_lo[(size_t)TOK * FF_];
__device__ __nv_bfloat16 g_wqkv_h[(size_t)3 * D_ * D_];
__device__ __nv_bfloat16 g_wqkv_l[(size_t)3 * D_ * D_];
__device__ __nv_bfloat16 g_wo_h[(size_t)D_ * D_];
__device__ __nv_bfloat16 g_wo_l[(size_t)D_ * D_];
__device__ __nv_bfloat16 g_w1_h[(size_t)FF_ * D_];
__device__ __nv_bfloat16 g_w1_l[(size_t)FF_ * D_];
__device__ __nv_bfloat16 g_w2_h[(size_t)D_ * FF_];
__device__ __nv_bfloat16 g_w2_l[(size_t)D_ * FF_];

// ---------------------------------------------------------------------------
// PTX helpers
// ---------------------------------------------------------------------------
#if HAS_TCGEN05
__device__ __forceinline__ uint32_t smem_u32_of(const void* p) {
    uint32_t a;
    asm("{ .reg .u64 t; cvta.to.shared.u64 t, %1; cvt.u32.u64 %0, t; }" : "=r"(a) : "l"(p));
    return a;
}
__device__ __forceinline__ void cp16(uint32_t dst, const void* src) {
    asm volatile("cp.async.cg.shared.global [%0], [%1], 16;" :: "r"(dst), "l"(src));
}
__device__ __forceinline__ void cp_async_arrive(uint32_t mbar) {
    asm volatile("cp.async.mbarrier.arrive.noinc.shared.b64 [%0];" :: "r"(mbar) : "memory");
}
__device__ __forceinline__ uint32_t sw128(uint32_t off) { return off ^ ((off >> 3) & 0x70); }

__device__ __forceinline__ uint64_t smem_desc(uint32_t addr) {
    constexpr uint64_t BASE = (uint64_t(2) << 61)   // SW128
                            | (uint64_t(1) << 46)   // Blackwell
                            | (uint64_t(64) << 32)  // SBO = 64
                            | (uint64_t(1) << 16);  // LBO = 1
    return BASE | ((uint64_t)(addr >> 4) & 0x3FFF);
}
// idesc: kind::f16, d=f32, a=bf16, b=bf16, M=128, N=256
#define GEMM_IDESC ((1u<<4) | (1u<<7) | (1u<<10) | ((256u/8)<<17) | ((128u/16)<<24))

__device__ __forceinline__ void mma_f16_ss(uint32_t d, uint64_t a, uint64_t b,
                                           uint32_t idesc, bool acc) {
    uint32_t e = acc ? 1u : 0u;
    asm volatile(
        "{\n\t.reg .pred p;\n\t"
        "setp.ne.u32 p, %4, 0;\n\t"
        "tcgen05.mma.cta_group::1.kind::f16 [%0], %1, %2, %3, {%5, %5, %5, %5}, p;\n\t}"
        :: "r"(d), "l"(a), "l"(b), "r"(idesc), "r"(e), "r"(0u) : "memory");
}
__device__ __forceinline__ void mbar_init(uint32_t addr, uint32_t cnt) {
    asm volatile("mbarrier.init.shared.b64 [%0], %1;" :: "r"(addr), "r"(cnt) : "memory");
}
__device__ __forceinline__ void mbar_wait(uint32_t addr, uint32_t parity) {
    asm volatile(
        "{\n\t.reg .pred P;\n\t"
        "W%=:\n\t"
        "mbarrier.try_wait.parity.acquire.cta.shared::cta.b64 P, [%0], %1, 0x989680;\n\t"
        "@!P bra W%=;\n\t}"
        :: "r"(addr), "r"(parity) : "memory");
}

#define TC_ALLOC(sm, n)   asm volatile("tcgen05.alloc.cta_group::1.sync.aligned.shared::cta.b32 [%0], %1;" :: "r"(sm), "r"(n) : "memory")
#define TC_RELINQ()       asm volatile("tcgen05.relinquish_alloc_permit.cta_group::1.sync.aligned;")
#define TC_DEALLOC(t, n)  asm volatile("tcgen05.dealloc.cta_group::1.sync.aligned.b32 %0, %1;" :: "r"(t), "r"(n))
#define TC_COMMIT(mb)     asm volatile("tcgen05.commit.cta_group::1.mbarrier::arrive::one.shared::cluster.b64 [%0];" :: "r"(mb) : "memory")
#define TC_FENCE_AFTER()  asm volatile("tcgen05.fence::after_thread_sync;" ::: "memory")
#define TC_FENCE_BEFORE() asm volatile("tcgen05.fence::before_thread_sync;" ::: "memory")
#define TC_WAIT_LD()      asm volatile("tcgen05.wait::ld.sync.aligned;" ::: "memory")
#define FENCE_ASYNC()     asm volatile("fence.proxy.async.shared::cta;" ::: "memory")

#define TC_LD_X32(r, t) \
    asm volatile( \
        "tcgen05.ld.sync.aligned.32x32b.x32.b32 " \
        "{%0, %1, %2, %3, %4, %5, %6, %7, " \
        " %8, %9, %10, %11, %12, %13, %14, %15, " \
        " %16, %17, %18, %19, %20, %21, %22, %23, " \
        " %24, %25, %26, %27, %28, %29, %30, %31}, [%32];" \
        : "=r"((r)[0]),  "=r"((r)[1]),  "=r"((r)[2]),  "=r"((r)[3]), \
          "=r"((r)[4]),  "=r"((r)[5]),  "=r"((r)[6]),  "=r"((r)[7]), \
          "=r"((r)[8]),  "=r"((r)[9]),  "=r"((r)[10]), "=r"((r)[11]), \
          "=r"((r)[12]), "=r"((r)[13]), "=r"((r)[14]), "=r"((r)[15]), \
          "=r"((r)[16]), "=r"((r)[17]), "=r"((r)[18]), "=r"((r)[19]), \
          "=r"((r)[20]), "=r"((r)[21]), "=r"((r)[22]), "=r"((r)[23]), \
          "=r"((r)[24]), "=r"((r)[25]), "=r"((r)[26]), "=r"((r)[27]), \
          "=r"((r)[28]), "=r"((r)[29]), "=r"((r)[30]), "=r"((r)[31]) \
        : "r"(t))
#endif  // HAS_TCGEN05

// ---------------------------------------------------------------------------
// fp32 -> bf16 (hi, lo) split helpers
// ---------------------------------------------------------------------------
__device__ __forceinline__ void split_store4(__nv_bfloat16* __restrict__ hi,
                                             __nv_bfloat16* __restrict__ lo,
                                             size_t idx, float4 v) {
    __nv_bfloat16 h0 = __float2bfloat16(v.x);
    __nv_bfloat16 h1 = __float2bfloat16(v.y);
    __nv_bfloat16 h2 = __float2bfloat16(v.z);
    __nv_bfloat16 h3 = __float2bfloat16(v.w);
    __nv_bfloat16 l0 = __float2bfloat16(v.x - __bfloat162float(h0));
    __nv_bfloat16 l1 = __float2bfloat16(v.y - __bfloat162float(h1));
    __nv_bfloat16 l2 = __float2bfloat16(v.z - __bfloat162float(h2));
    __nv_bfloat16 l3 = __float2bfloat16(v.w - __bfloat162float(h3));
    __nv_bfloat162 ha; ha.x = h0; ha.y = h1;
    __nv_bfloat162 hb; hb.x = h2; hb.y = h3;
    __nv_bfloat162 la; la.x = l0; la.y = l1;
    __nv_bfloat162 lb; lb.x = l2; lb.y = l3;
    *(__nv_bfloat162*)(hi + idx)     = ha;
    *(__nv_bfloat162*)(hi + idx + 2) = hb;
    *(__nv_bfloat162*)(lo + idx)     = la;
    *(__nv_bfloat162*)(lo + idx + 2) = lb;
}

__global__ __launch_bounds__(256)
void split_kernel(const float* __restrict__ x,
                  __nv_bfloat16* __restrict__ hi,
                  __nv_bfloat16* __restrict__ lo, int n4)
{
    int i = blockIdx.x * 256 + threadIdx.x;
    if (i < n4) {
        float4 v = ((const float4*)x)[i];
        split_store4(hi, lo, (size_t)i * 4, v);
    }
}

// ---------------------------------------------------------------------------
// LayerNorm fused with bf16 split output
// ---------------------------------------------------------------------------
__global__ __launch_bounds__(256)
void ln_split_kernel(const float* __restrict__ x,
                     const float* __restrict__ gw,
                     const float* __restrict__ bw,
                     __nv_bfloat16* __restrict__ out_hi,
                     __nv_bfloat16* __restrict__ out_lo)
{
    __shared__ float red[16];
    const int row = blockIdx.x;
    const int tid = threadIdx.x;

    const float4 v = ((const float4*)(x + (size_t)row * D_))[tid];
    float s  = v.x + v.y + v.z + v.w;
    float ss = v.x*v.x + v.y*v.y + v.z*v.z + v.w*v.w;

    #pragma unroll
    for (int o = 16; o; o >>= 1) {
        s  += __shfl_xor_sync(0xffffffffu, s,  o);
        ss += __shfl_xor_sync(0xffffffffu, ss, o);
    }
    const int wid = tid >> 5, lid = tid & 31;
    if (lid == 0) { red[wid] = s; red[8 + wid] = ss; }
    __syncthreads();

    float sum = 0.f, sq = 0.f;
    #pragma unroll
    for (int i = 0; i < 8; i++) { sum += red[i]; sq += red[8 + i]; }

    const float mu  = sum * (1.0f / D_);
    const float var = sq  * (1.0f / D_) - mu * mu;
    const float rs  = rsqrtf(var + 1e-5f);

    const float4 g4 = ((const float4*)gw)[tid];
    const float4 b4 = ((const float4*)bw)[tid];
    float4 o;
    o.x = (v.x - mu) * rs * g4.x + b4.x;
    o.y = (v.y - mu) * rs * g4.y + b4.y;
    o.z = (v.z - mu) * rs * g4.z + b4.z;
    o.w = (v.w - mu) * rs * g4.w + b4.w;
    split_store4(out_hi, out_lo, (size_t)row * D_ + tid * 4, o);
}

// ---------------------------------------------------------------------------
// GEMM (TN), warp-specialized tcgen05, 128x256 tile, N=256 MMAs.
//   - 256 threads. Warps 4-7: cp.async producers (mbarrier-tracked, no
//     wait_group). Thread 0: MMA issuer. All 8 warps: epilogue.
//   - 2 stages x 96KB (BK=64): [Ah 16K][Al 16K][Bh 32K][Bl 32K].
//   - full[s]: 128 .noinc cp.async arrivals; done[s]: tcgen05.commit
//     (stage recycling, in-order waits); fin: single-phase final commit.
// ---------------------------------------------------------------------------
enum { EPI_BIAS = 0, EPI_BIAS_RES = 1, EPI_GELU_SPLIT = 2 };

__device__ __forceinline__ float gelu_tanh(float x)
{
    const float u = 0.7978845608028654f * (x + 0.044715f * x * x * x);
    return 0.5f * x * (1.0f + tanhf(u));
}

#define STAGE_BYTES 98304
#define SMEM_GEMM   (1024 + 2 * STAGE_BYTES)

#if HAS_TCGEN05
__device__ __forceinline__ void stage_load(uint32_t smem_base, int s, int kt,
                                           const __nv_bfloat16* __restrict__ Ah,
                                           const __nv_bfloat16* __restrict__ Al,
                                           const __nv_bfloat16* __restrict__ Bh,
                                           const __nv_bfloat16* __restrict__ Bl,
                                           int m0, int n0, int K, int ptid)
{
    const uint32_t sb = smem_base + 1024 + s * STAGE_BYTES;
    const int r = ptid;                         // 0..127
    // A row r (128 rows)
    {
        const size_t ka = (size_t)(m0 + r) * K + (size_t)kt * 64;
        const __nv_bfloat16* pah = Ah + ka;
        const __nv_bfloat16* pal = Al + ka;
        #pragma unroll
        for (int c = 0; c < 8; c++) {
            const uint32_t so = sw128((uint32_t)(r * 128 + c * 16));
            cp16(sb + so,         pah + c * 8);
            cp16(sb + 16384 + so, pal + c * 8);
        }
    }
    // B rows r and r+128 (256 rows)
    #pragma unroll
    for (int h = 0; h < 2; h++) {
        const int rr = r + h * 128;
        const size_t kb = (size_t)(n0 + rr) * K + (size_t)kt * 64;
        const __nv_bfloat16* pbh = Bh + kb;
        const __nv_bfloat16* pbl = Bl + kb;
        #pragma unroll
        for (int c = 0; c < 8; c++) {
            const uint32_t so = sw128((uint32_t)(rr * 128 + c * 16));
            cp16(sb + 32768 + so, pbh + c * 8);
            cp16(sb + 65536 + so, pbl + c * 8);
        }
    }
}
#endif

template <int EPI>
__global__ __launch_bounds__(256, 1)
void gemm_tc(const __nv_bfloat16* __restrict__ Ah, const __nv_bfloat16* __restrict__ Al,
             const __nv_bfloat16* __restrict__ Bh, const __nv_bfloat16* __restrict__ Bl,
             const float* __restrict__ bias, const float* __restrict__ resid,
             float* __restrict__ Cf,
             __nv_bfloat16* __restrict__ Chi, __nv_bfloat16* __restrict__ Clo,
             int N, int K)
{
#if HAS_TCGEN05
    extern __shared__ char smem[];
    const uint32_t sm = smem_u32_of(smem);
    const int tid = threadIdx.x;
    const int wid = tid >> 5;
    const int lid = tid & 31;
    const int m0 = blockIdx.y * 128;
    const int n0 = blockIdx.x * 256;
    const int T  = K >> 6;                 // K / 64

    // barriers: done[s] sm+8+8s (count 1); full[s] sm+32+8s (count 128, noinc);
    //           fin sm+56 (count 1, single phase)
    if (tid == 0) {
        mbar_init(sm + 8,  1);   mbar_init(sm + 16, 1);
        mbar_init(sm + 32, 128); mbar_init(sm + 40, 128);
        mbar_init(sm + 56, 1);
    }
    if (wid == 0) {
        TC_ALLOC(sm, 256);
        TC_RELINQ();
    }
    __syncthreads();

    uint32_t tmem;
    asm volatile("ld.shared.b32 %0, [%1];" : "=r"(tmem) : "r"(sm));

    if (wid >= 4) {
        // ------------------------- producers -------------------------------
        const int ptid = tid - 128;
        for (int t = 0; t < T; ++t) {
            const int s = t & 1;
            if (t >= 2) mbar_wait(sm + 8 + s * 8, ((t >> 1) - 1) & 1);
            stage_load(sm, s, t, Ah, Al, Bh, Bl, m0, n0, K, ptid);
            cp_async_arrive(sm + 32 + s * 8);
        }
    } else if (tid == 0) {
        // ------------------------- MMA issuer ------------------------------
        uint64_t dAh[2], dAl[2], dBh[2], dBl[2];
        #pragma unroll
        for (int s = 0; s < 2; s++) {
            const uint32_t sb = sm + 1024 + s * STAGE_BYTES;
            dAh[s] = smem_desc(sb);
            dAl[s] = smem_desc(sb + 16384);
            dBh[s] = smem_desc(sb + 32768);
            dBl[s] = smem_desc(sb + 65536);
        }
        for (int t = 0; t < T; ++t) {
            const int s = t & 1;
            mbar_wait(sm + 32 + s * 8, (t >> 1) & 1);
            FENCE_ASYNC();
            #pragma unroll
            for (int ks = 0; ks < 4; ks++) {
                mma_f16_ss(tmem, dAh[s] + ks*2, dBh[s] + ks*2, GEMM_IDESC, !(t == 0 && ks == 0));
                mma_f16_ss(tmem, dAh[s] + ks*2, dBl[s] + ks*2, GEMM_IDESC, true);
                mma_f16_ss(tmem, dAl[s] + ks*2, dBh[s] + ks*2, GEMM_IDESC, true);
            }
            TC_COMMIT(sm + 8 + s * 8);
        }
        TC_COMMIT(sm + 56);  // single-phase completion of ALL issued MMAs
    }

    // ALL threads wait the single-phase fin barrier (no parity aliasing)
    mbar_wait(sm + 56, 0);
    TC_FENCE_AFTER();

    // epilogue: warp w -> rows (w&3)*32+lid, column blocks (w>>2)*4 + {0..3}
    const int m = m0 + (wid & 3) * 32 + lid;
    const int cb0 = (wid >> 2) * 4;
    #pragma unroll
    for (int cc = 0; cc < 4; cc++) {
        const int cb = cb0 + cc;
        uint32_t dr[32];
        TC_LD_X32(dr, tmem + cb * 32);
        TC_WAIT_LD();
        const int nb = n0 + cb * 32;
        if (EPI == EPI_GELU_SPLIT) {
            #pragma unroll
            for (int j = 0; j < 32; j += 4) {
                float4 v;
                v.x = gelu_tanh(__uint_as_float(dr[j])     + bias[nb + j]);
                v.y = gelu_tanh(__uint_as_float(dr[j + 1]) + bias[nb + j + 1]);
                v.z = gelu_tanh(__uint_as_float(dr[j + 2]) + bias[nb + j + 2]);
                v.w = gelu_tanh(__uint_as_float(dr[j + 3]) + bias[nb + j + 3]);
                split_store4(Chi, Clo, (size_t)m * N + nb + j, v);
            }
        } else {
            #pragma unroll
            for (int j = 0; j < 32; j += 4) {
                float4 v;
                v.x = __uint_as_float(dr[j])     + bias[nb + j];
                v.y = __uint_as_float(dr[j + 1]) + bias[nb + j + 1];
                v.z = __uint_as_float(dr[j + 2]) + bias[nb + j + 2];
                v.w = __uint_as_float(dr[j + 3]) + bias[nb + j + 3];
                if (EPI == EPI_BIAS_RES) {
                    const float4 rr = *(const float4*)(resid + (size_t)m * N + nb + j);
                    v.x += rr.x; v.y += rr.y; v.z += rr.z; v.w += rr.w;
                }
                *(float4*)(Cf + (size_t)m * N + nb + j) = v;
            }
        }
    }
    TC_FENCE_BEFORE();
    __syncthreads();
    if (wid == 0) TC_DEALLOC(tmem, 256);

#else  // ------------------- portable SIMT fallback (256 threads) ----------
    extern __shared__ char smem[];
    float* As = (float*)smem;                       // [16][128] k-major
    float* Bs = (float*)(smem + 16 * 128 * 4);      // [16][128]
    const int tid = threadIdx.x;
    const int m0 = blockIdx.y * 128;
    const int ty = tid >> 4;   // 0..15
    const int tx = tid & 15;   // 0..15

    for (int nh = 0; nh < 2; nh++) {
        const int n0 = blockIdx.x * 256 + nh * 128;
        float acc[8][8];
        #pragma unroll
        for (int i = 0; i < 8; i++)
            #pragma unroll
            for (int j = 0; j < 8; j++) acc[i][j] = 0.f;

        for (int k0 = 0; k0 < K; k0 += 16) {
            __syncthreads();
            #pragma unroll 4
            for (int i = tid; i < 2048; i += 256) {
                const int r = i >> 4, c = i & 15;
                const size_t gia = (size_t)(m0 + r) * K + k0 + c;
                As[c * 128 + r] = __bfloat162float(Ah[gia]) + __bfloat162float(Al[gia]);
                const size_t gib = (size_t)(n0 + r) * K + k0 + c;
                Bs[c * 128 + r] = __bfloat162float(Bh[gib]) + __bfloat162float(Bl[gib]);
            }
            __syncthreads();
            #pragma unroll
            for (int kk = 0; kk < 16; kk++) {
                float a[8], b[8];
                #pragma unroll
                for (int i = 0; i < 8; i++) a[i] = As[kk * 128 + ty * 8 + i];
                #pragma unroll
                for (int j = 0; j < 8; j++) b[j] = Bs[kk * 128 + tx * 8 + j];
                #pragma unroll
                for (int i = 0; i < 8; i++)
                    #pragma unroll
                    for (int j = 0; j < 8; j++)
                        acc[i][j] = fmaf(a[i], b[j], acc[i][j]);
            }
        }

        #pragma unroll
        for (int i = 0; i < 8; i++) {
            const int m = m0 + ty * 8 + i;
            #pragma unroll
            for (int j = 0; j < 8; j++) {
                const int n = n0 + tx * 8 + j;
                float v = acc[i][j] + bias[n];
                if (EPI == EPI_GELU_SPLIT) {
                    v = gelu_tanh(v);
                    __nv_bfloat16 hv = __float2bfloat16(v);
                    Chi[(size_t)m * N + n] = hv;
                    Clo[(size_t)m * N + n] = __float2bfloat16(v - __bfloat162float(hv));
                } else {
                    if (EPI == EPI_BIAS_RES) v += resid[(size_t)m * N + n];
                    Cf[(size_t)m * N + n] = v;
                }
            }
        }
        __syncthreads();
    }
#endif
}

// ---------------------------------------------------------------------------
// Causal flash attention, fp32 math; output written as bf16 (hi, lo) split.
// ---------------------------------------------------------------------------
__global__ __launch_bounds__(64)
void attn_kernel(const float* __restrict__ qkv,
                 __nv_bfloat16* __restrict__ out_hi,
                 __nv_bfloat16* __restrict__ out_lo)
{
    __shared__ float k_s[64][68];
    __shared__ float v_s[64][64];

    const int qt = blockIdx.x;
    const int bh = blockIdx.y;
    const int b  = bh >> 4;
    const int h  = bh & 15;
    const int t  = threadIdx.x;

    const size_t seq_base = (size_t)b * S_ * (3 * D_);
    const size_t head_off = (size_t)h * DH_;

    float q[64];
    {
        const float* qp = qkv + seq_base + head_off + (size_t)(qt * 64 + t) * (3 * D_);
        #pragma unroll
        for (int d = 0; d < 64; d += 4) {
            const float4 u = *(const float4*)(qp + d);
            q[d] = u.x; q[d+1] = u.y; q[d+2] = u.z; q[d+3] = u.w;
        }
    }

    float o[64];
    #pragma unroll
    for (int d = 0; d < 64; d++) o[d] = 0.f;
    float m = -1e30f, l = 0.f;

    for (int kt = 0; kt <= qt; kt++) {
        const float* kp = qkv + seq_base + D_     + head_off + (size_t)(kt * 64) * (3 * D_);
        const float* vp = qkv + seq_base + 2 * D_ + head_off + (size_t)(kt * 64) * (3 * D_);
        #pragma unroll 4
        for (int i = t; i < 64 * 16; i += 64) {
            const int r = i >> 4;
            const int c = (i & 15) << 2;
            const float4 kv = *(const float4*)(kp + (size_t)r * (3 * D_) + c);
            *(float4*)&k_s[r][c] = kv;
            const float4 vv = *(const float4*)(vp + (size_t)r * (3 * D_) + c);
            *(float4*)&v_s[r][c] = vv;
        }
        __syncthreads();

        const bool diag = (kt == qt);
        #pragma unroll
        for (int half = 0; half < 2; half++) {
            const int kbase = half * 32;
            float s[32];
            float mt = -1e30f;
            #pragma unroll 2
            for (int kc = 0; kc < 32; kc++) {
                const float4* krow = (const float4*)k_s[kbase + kc];
                float d0 = 0.f, d1 = 0.f, d2 = 0.f, d3 = 0.f;
                #pragma unroll
                for (int d4 = 0; d4 < 16; d4++) {
                    const float4 kv = krow[d4];
                    d0 = fmaf(q[4*d4+0], kv.x, d0);
                    d1 = fmaf(q[4*d4+1], kv.y, d1);
                    d2 = fmaf(q[4*d4+2], kv.z, d2);
                    d3 = fmaf(q[4*d4+3], kv.w, d3);
                }
                float sc = (d0 + d1 + d2 + d3) * 0.125f;
                if (diag && (kbase + kc) > t) sc = -1e30f;
                s[kc] = sc;
                mt = fmaxf(mt, sc);
            }
            const float m_new = fmaxf(m, mt);
            const float corr  = __expf(m - m_new);
            l *= corr;
            #pragma unroll
            for (int d = 0; d < 64; d++) o[d] *= corr;
            #pragma unroll 2
            for (int kc = 0; kc < 32; kc++) {
                const float p = __expf(s[kc] - m_new);
                l += p;
                const float4* vrow = (const float4*)v_s[kbase + kc];
                #pragma unroll
                for (int d4 = 0; d4 < 16; d4++) {
                    const float4 vv = vrow[d4];
                    o[4*d4+0] = fmaf(p, vv.x, o[4*d4+0]);
                    o[4*d4+1] = fmaf(p, vv.y, o[4*d4+1]);
                    o[4*d4+2] = fmaf(p, vv.z, o[4*d4+2]);
                    o[4*d4+3] = fmaf(p, vv.w, o[4*d4+3]);
                }
            }
            m = m_new;
        }
        __syncthreads();
    }

    const float inv_l = 1.0f / l;
    #pragma unroll
    for (int d4 = 0; d4 < 16; d4++) {
        float4 w;
        w.x = o[4*d4+0] * inv_l;
        w.y = o[4*d4+1] * inv_l;
        w.z = o[4*d4+2] * inv_l;
        w.w = o[4*d4+3] * inv_l;
        *(float4*)&k_s[t][4*d4] = w;
    }
    __syncthreads();
    const size_t out_base = ((size_t)b * S_ + qt * 64) * D_ + head_off;
    #pragma unroll 4
    for (int i = t; i < 64 * 16; i += 64) {
        const int r = i >> 4;
        const int c = (i & 15) << 2;
        float4 w;
        w.x = k_s[r][c]; w.y = k_s[r][c+1]; w.z = k_s[r][c+2]; w.w = k_s[r][c+3];
        split_store4(out_hi, out_lo, out_base + (size_t)r * D_ + c, w);
    }
}

// ---------------------------------------------------------------------------
// Launch
// ---------------------------------------------------------------------------
extern "C" void kernel_launch(void* const* d_in, const int* in_sizes, int n_in,
                              void* d_out, int out_size)
{
    const float* x     = (const float*)d_in[0];
    const float* ln1_g = (const float*)d_in[1];
    const float* ln1_b = (const float*)d_in[2];
    const float* w_qkv = (const float*)d_in[3];
    const float* b_qkv = (const float*)d_in[4];
    const float* w_o   = (const float*)d_in[5];
    const float* b_o   = (const float*)d_in[6];
    const float* ln2_g = (const float*)d_in[7];
    const float* ln2_b = (const float*)d_in[8];
    const float* w1    = (const float*)d_in[9];
    const float* b1    = (const float*)d_in[10];
    const float* w2    = (const float*)d_in[11];
    const float* b2    = (const float*)d_in[12];
    float* out = (float*)d_out;

    static bool inited = false;
    static float *p_qkv, *p_x2;
    static __nv_bfloat16 *p_act_h, *p_act_l, *p_big_h, *p_big_l;
    static __nv_bfloat16 *p_wqkv_h, *p_wqkv_l, *p_wo_h, *p_wo_l;
    static __nv_bfloat16 *p_w1_h, *p_w1_l, *p_w2_h, *p_w2_l;
    if (!inited) {
        void* p;
        cudaGetSymbolAddress(&p, g_qkv);    p_qkv    = (float*)p;
        cudaGetSymbolAddress(&p, g_x2);     p_x2     = (float*)p;
        cudaGetSymbolAddress(&p, g_act_hi); p_act_h  = (__nv_bfloat16*)p;
        cudaGetSymbolAddress(&p, g_act_lo); p_act_l  = (__nv_bfloat16*)p;
        cudaGetSymbolAddress(&p, g_big_hi); p_big_h  = (__nv_bfloat16*)p;
        cudaGetSymbolAddress(&p, g_big_lo); p_big_l  = (__nv_bfloat16*)p;
        cudaGetSymbolAddress(&p, g_wqkv_h); p_wqkv_h = (__nv_bfloat16*)p;
        cudaGetSymbolAddress(&p, g_wqkv_l); p_wqkv_l = (__nv_bfloat16*)p;
        cudaGetSymbolAddress(&p, g_wo_h);   p_wo_h   = (__nv_bfloat16*)p;
        cudaGetSymbolAddress(&p, g_wo_l);   p_wo_l   = (__nv_bfloat16*)p;
        cudaGetSymbolAddress(&p, g_w1_h);   p_w1_h   = (__nv_bfloat16*)p;
        cudaGetSymbolAddress(&p, g_w1_l);   p_w1_l   = (__nv_bfloat16*)p;
        cudaGetSymbolAddress(&p, g_w2_h);   p_w2_h   = (__nv_bfloat16*)p;
        cudaGetSymbolAddress(&p, g_w2_l);   p_w2_l   = (__nv_bfloat16*)p;
        cudaFuncSetAttribute(gemm_tc<EPI_BIAS>,       cudaFuncAttributeMaxDynamicSharedMemorySize, SMEM_GEMM);
        cudaFuncSetAttribute(gemm_tc<EPI_BIAS_RES>,   cudaFuncAttributeMaxDynamicSharedMemorySize, SMEM_GEMM);
        cudaFuncSetAttribute(gemm_tc<EPI_GELU_SPLIT>, cudaFuncAttributeMaxDynamicSharedMemorySize, SMEM_GEMM);
        inited = true;
    }

    // 0. weight splits
    split_kernel<<<(3*D_*D_/4 + 255)/256, 256>>>(w_qkv, p_wqkv_h, p_wqkv_l, 3*D_*D_/4);
    split_kernel<<<(D_*D_/4   + 255)/256, 256>>>(w_o,   p_wo_h,   p_wo_l,   D_*D_/4);
    split_kernel<<<(FF_*D_/4  + 255)/256, 256>>>(w1,    p_w1_h,   p_w1_l,   FF_*D_/4);
    split_kernel<<<(D_*FF_/4  + 255)/256, 256>>>(w2,    p_w2_h,   p_w2_l,   D_*FF_/4);

    // 1. LN1 + split
    ln_split_kernel<<<TOK, 256>>>(x, ln1_g, ln1_b, p_act_h, p_act_l);

    // 2. QKV projection
    gemm_tc<EPI_BIAS><<<dim3(3*D_/256, TOK/128), 256, SMEM_GEMM>>>(
        p_act_h, p_act_l, p_wqkv_h, p_wqkv_l, b_qkv, nullptr,
        p_qkv, nullptr, nullptr, 3*D_, D_);

    // 3. causal attention
    attn_kernel<<<dim3(S_/64, B_*H_), 64>>>(p_qkv, p_act_h, p_act_l);

    // 4. output projection + residual
    gemm_tc<EPI_BIAS_RES><<<dim3(D_/256, TOK/128), 256, SMEM_GEMM>>>(
        p_act_h, p_act_l, p_wo_h, p_wo_l, b_o, x,
        p_x2, nullptr, nullptr, D_, D_);

    // 5. LN2 + split
    ln_split_kernel<<<TOK, 256>>>(p_x2, ln2_g, ln2_b, p_act_h, p_act_l);

    // 6. FFN up + GELU + split
    gemm_tc<EPI_GELU_SPLIT><<<dim3(FF_/256, TOK/128), 256, SMEM_GEMM>>>(
        p_act_h, p_act_l, p_w1_h, p_w1_l, b1, nullptr,
        nullptr, p_big_h, p_big_l, FF_, D_);

    // 7. FFN down + residual -> out
    gemm_tc<EPI_BIAS_RES><<<dim3(D_/256, TOK/128), 256, SMEM_GEMM>>>(
        p_big_h, p_big_l, p_w2_h, p_w2_l, b2, p_x2,
        out, nullptr, nullptr, D_, FF_);
}

// round 7
// speedup vs baseline: 2.5373x; 1.0965x over previous
#include <cuda_runtime.h>
#include <cuda_bf16.h>
#include <math.h>
#include <stdint.h>

// ---------------------------------------------------------------------------
// Per-compilation-pass feature detection (plain compute_103 pass gets fallback)
// ---------------------------------------------------------------------------
#if defined(__CUDA_ARCH__)
# if defined(__CUDA_ARCH_FEAT_SM103_ALL) || defined(__CUDA_ARCH_FEAT_SM100_ALL) || \
     (defined(__CUDA_ARCH_FAMILY_SPECIFIC__) && (__CUDA_ARCH_FAMILY_SPECIFIC__ >= 1000))
#  define HAS_TCGEN05 1
# else
#  define HAS_TCGEN05 0
# endif
#else
# define HAS_TCGEN05 0
#endif

// ---------------------------------------------------------------------------
// Problem constants
// ---------------------------------------------------------------------------
#define B_    8
#define S_    1024
#define D_    1024
#define H_    16
#define DH_   64
#define FF_   4096
#define TOK   (B_ * S_)

// ---------------------------------------------------------------------------
// Scratch
// ---------------------------------------------------------------------------
__device__ float g_qkv[(size_t)TOK * 3 * D_];
__device__ float g_x2 [(size_t)TOK * D_];
__device__ __nv_bfloat16 g_act_hi[(size_t)TOK * D_];
__device__ __nv_bfloat16 g_act_lo[(size_t)TOK * D_];
__device__ __nv_bfloat16 g_big_hi[(size_t)TOK * FF_];
__device__ __nv_bfloat16 g_big_lo[(size_t)TOK * FF_];
__device__ __nv_bfloat16 g_wqkv_h[(size_t)3 * D_ * D_];
__device__ __nv_bfloat16 g_wqkv_l[(size_t)3 * D_ * D_];
__device__ __nv_bfloat16 g_wo_h[(size_t)D_ * D_];
__device__ __nv_bfloat16 g_wo_l[(size_t)D_ * D_];
__device__ __nv_bfloat16 g_w1_h[(size_t)FF_ * D_];
__device__ __nv_bfloat16 g_w1_l[(size_t)FF_ * D_];
__device__ __nv_bfloat16 g_w2_h[(size_t)D_ * FF_];
__device__ __nv_bfloat16 g_w2_l[(size_t)D_ * FF_];

// ---------------------------------------------------------------------------
// PTX helpers
// ---------------------------------------------------------------------------
#if HAS_TCGEN05
__device__ __forceinline__ uint32_t smem_u32_of(const void* p) {
    uint32_t a;
    asm("{ .reg .u64 t; cvta.to.shared.u64 t, %1; cvt.u32.u64 %0, t; }" : "=r"(a) : "l"(p));
    return a;
}
__device__ __forceinline__ void cp16(uint32_t dst, const void* src) {
    asm volatile("cp.async.cg.shared.global [%0], [%1], 16;" :: "r"(dst), "l"(src));
}
__device__ __forceinline__ void cp_async_arrive(uint32_t mbar) {
    asm volatile("cp.async.mbarrier.arrive.noinc.shared.b64 [%0];" :: "r"(mbar) : "memory");
}
__device__ __forceinline__ uint32_t sw128(uint32_t off) { return off ^ ((off >> 3) & 0x70); }

__device__ __forceinline__ uint64_t smem_desc(uint32_t addr) {
    constexpr uint64_t BASE = (uint64_t(2) << 61)   // SW128
                            | (uint64_t(1) << 46)   // Blackwell
                            | (uint64_t(64) << 32)  // SBO = 64
                            | (uint64_t(1) << 16);  // LBO = 1
    return BASE | ((uint64_t)(addr >> 4) & 0x3FFF);
}
// idesc: kind::f16, d=f32, a=bf16, b=bf16, M=128, N=256
#define GEMM_IDESC ((1u<<4) | (1u<<7) | (1u<<10) | ((256u/8)<<17) | ((128u/16)<<24))

__device__ __forceinline__ void mma_f16_ss(uint32_t d, uint64_t a, uint64_t b,
                                           uint32_t idesc, bool acc) {
    uint32_t e = acc ? 1u : 0u;
    asm volatile(
        "{\n\t.reg .pred p;\n\t"
        "setp.ne.u32 p, %4, 0;\n\t"
        "tcgen05.mma.cta_group::1.kind::f16 [%0], %1, %2, %3, {%5, %5, %5, %5}, p;\n\t}"
        :: "r"(d), "l"(a), "l"(b), "r"(idesc), "r"(e), "r"(0u) : "memory");
}
__device__ __forceinline__ void mbar_init(uint32_t addr, uint32_t cnt) {
    asm volatile("mbarrier.init.shared.b64 [%0], %1;" :: "r"(addr), "r"(cnt) : "memory");
}
__device__ __forceinline__ void mbar_wait(uint32_t addr, uint32_t parity) {
    asm volatile(
        "{\n\t.reg .pred P;\n\t"
        "W%=:\n\t"
        "mbarrier.try_wait.parity.acquire.cta.shared::cta.b64 P, [%0], %1, 0x989680;\n\t"
        "@!P bra W%=;\n\t}"
        :: "r"(addr), "r"(parity) : "memory");
}

#define TC_ALLOC(sm, n)   asm volatile("tcgen05.alloc.cta_group::1.sync.aligned.shared::cta.b32 [%0], %1;" :: "r"(sm), "r"(n) : "memory")
#define TC_RELINQ()       asm volatile("tcgen05.relinquish_alloc_permit.cta_group::1.sync.aligned;")
#define TC_DEALLOC(t, n)  asm volatile("tcgen05.dealloc.cta_group::1.sync.aligned.b32 %0, %1;" :: "r"(t), "r"(n))
#define TC_COMMIT(mb)     asm volatile("tcgen05.commit.cta_group::1.mbarrier::arrive::one.shared::cluster.b64 [%0];" :: "r"(mb) : "memory")
#define TC_FENCE_AFTER()  asm volatile("tcgen05.fence::after_thread_sync;" ::: "memory")
#define TC_FENCE_BEFORE() asm volatile("tcgen05.fence::before_thread_sync;" ::: "memory")
#define TC_WAIT_LD()      asm volatile("tcgen05.wait::ld.sync.aligned;" ::: "memory")
#define FENCE_ASYNC()     asm volatile("fence.proxy.async.shared::cta;" ::: "memory")

#define TC_LD_X32(r, t) \
    asm volatile( \
        "tcgen05.ld.sync.aligned.32x32b.x32.b32 " \
        "{%0, %1, %2, %3, %4, %5, %6, %7, " \
        " %8, %9, %10, %11, %12, %13, %14, %15, " \
        " %16, %17, %18, %19, %20, %21, %22, %23, " \
        " %24, %25, %26, %27, %28, %29, %30, %31}, [%32];" \
        : "=r"((r)[0]),  "=r"((r)[1]),  "=r"((r)[2]),  "=r"((r)[3]), \
          "=r"((r)[4]),  "=r"((r)[5]),  "=r"((r)[6]),  "=r"((r)[7]), \
          "=r"((r)[8]),  "=r"((r)[9]),  "=r"((r)[10]), "=r"((r)[11]), \
          "=r"((r)[12]), "=r"((r)[13]), "=r"((r)[14]), "=r"((r)[15]), \
          "=r"((r)[16]), "=r"((r)[17]), "=r"((r)[18]), "=r"((r)[19]), \
          "=r"((r)[20]), "=r"((r)[21]), "=r"((r)[22]), "=r"((r)[23]), \
          "=r"((r)[24]), "=r"((r)[25]), "=r"((r)[26]), "=r"((r)[27]), \
          "=r"((r)[28]), "=r"((r)[29]), "=r"((r)[30]), "=r"((r)[31]) \
        : "r"(t))

// ---- packed f32x2 (Blackwell) ----
__device__ __forceinline__ uint64_t pack2f(float lo, float hi) {
    uint64_t r;
    asm("mov.b64 %0, {%1, %2};" : "=l"(r) : "f"(lo), "f"(hi));
    return r;
}
__device__ __forceinline__ void unpack2f(uint64_t v, float& lo, float& hi) {
    asm("mov.b64 {%0, %1}, %2;" : "=f"(lo), "=f"(hi) : "l"(v));
}
__device__ __forceinline__ void ffma2(uint64_t& d, uint64_t a, uint64_t b) {
    asm("fma.rn.f32x2 %0, %1, %2, %3;" : "=l"(d) : "l"(a), "l"(b), "l"(d));
}
__device__ __forceinline__ void fadd2(uint64_t& d, uint64_t a) {
    asm("add.rn.f32x2 %0, %1, %2;" : "=l"(d) : "l"(d), "l"(a));
}
__device__ __forceinline__ void fmul2(uint64_t& d, uint64_t a) {
    asm("mul.rn.f32x2 %0, %1, %2;" : "=l"(d) : "l"(d), "l"(a));
}
#endif  // HAS_TCGEN05

// ---------------------------------------------------------------------------
// fp32 -> bf16 (hi, lo) split helpers
// ---------------------------------------------------------------------------
__device__ __forceinline__ void split_store4(__nv_bfloat16* __restrict__ hi,
                                             __nv_bfloat16* __restrict__ lo,
                                             size_t idx, float4 v) {
    __nv_bfloat16 h0 = __float2bfloat16(v.x);
    __nv_bfloat16 h1 = __float2bfloat16(v.y);
    __nv_bfloat16 h2 = __float2bfloat16(v.z);
    __nv_bfloat16 h3 = __float2bfloat16(v.w);
    __nv_bfloat16 l0 = __float2bfloat16(v.x - __bfloat162float(h0));
    __nv_bfloat16 l1 = __float2bfloat16(v.y - __bfloat162float(h1));
    __nv_bfloat16 l2 = __float2bfloat16(v.z - __bfloat162float(h2));
    __nv_bfloat16 l3 = __float2bfloat16(v.w - __bfloat162float(h3));
    __nv_bfloat162 ha; ha.x = h0; ha.y = h1;
    __nv_bfloat162 hb; hb.x = h2; hb.y = h3;
    __nv_bfloat162 la; la.x = l0; la.y = l1;
    __nv_bfloat162 lb; lb.x = l2; lb.y = l3;
    *(__nv_bfloat162*)(hi + idx)     = ha;
    *(__nv_bfloat162*)(hi + idx + 2) = hb;
    *(__nv_bfloat162*)(lo + idx)     = la;
    *(__nv_bfloat162*)(lo + idx + 2) = lb;
}

__global__ __launch_bounds__(256)
void split_kernel(const float* __restrict__ x,
                  __nv_bfloat16* __restrict__ hi,
                  __nv_bfloat16* __restrict__ lo, int n4)
{
    int i = blockIdx.x * 256 + threadIdx.x;
    if (i < n4) {
        float4 v = ((const float4*)x)[i];
        split_store4(hi, lo, (size_t)i * 4, v);
    }
}

// ---------------------------------------------------------------------------
// LayerNorm fused with bf16 split output
// ---------------------------------------------------------------------------
__global__ __launch_bounds__(256)
void ln_split_kernel(const float* __restrict__ x,
                     const float* __restrict__ gw,
                     const float* __restrict__ bw,
                     __nv_bfloat16* __restrict__ out_hi,
                     __nv_bfloat16* __restrict__ out_lo)
{
    __shared__ float red[16];
    const int row = blockIdx.x;
    const int tid = threadIdx.x;

    const float4 v = ((const float4*)(x + (size_t)row * D_))[tid];
    float s  = v.x + v.y + v.z + v.w;
    float ss = v.x*v.x + v.y*v.y + v.z*v.z + v.w*v.w;

    #pragma unroll
    for (int o = 16; o; o >>= 1) {
        s  += __shfl_xor_sync(0xffffffffu, s,  o);
        ss += __shfl_xor_sync(0xffffffffu, ss, o);
    }
    const int wid = tid >> 5, lid = tid & 31;
    if (lid == 0) { red[wid] = s; red[8 + wid] = ss; }
    __syncthreads();

    float sum = 0.f, sq = 0.f;
    #pragma unroll
    for (int i = 0; i < 8; i++) { sum += red[i]; sq += red[8 + i]; }

    const float mu  = sum * (1.0f / D_);
    const float var = sq  * (1.0f / D_) - mu * mu;
    const float rs  = rsqrtf(var + 1e-5f);

    const float4 g4 = ((const float4*)gw)[tid];
    const float4 b4 = ((const float4*)bw)[tid];
    float4 o;
    o.x = (v.x - mu) * rs * g4.x + b4.x;
    o.y = (v.y - mu) * rs * g4.y + b4.y;
    o.z = (v.z - mu) * rs * g4.z + b4.z;
    o.w = (v.w - mu) * rs * g4.w + b4.w;
    split_store4(out_hi, out_lo, (size_t)row * D_ + tid * 4, o);
}

// ---------------------------------------------------------------------------
// GEMM (TN), warp-specialized tcgen05, 128x256 tile, N=256 MMAs (unchanged
// from round 6 — proven correct and fastest so far).
// ---------------------------------------------------------------------------
enum { EPI_BIAS = 0, EPI_BIAS_RES = 1, EPI_GELU_SPLIT = 2 };

__device__ __forceinline__ float gelu_tanh(float x)
{
    const float u = 0.7978845608028654f * (x + 0.044715f * x * x * x);
    return 0.5f * x * (1.0f + tanhf(u));
}

#define STAGE_BYTES 98304
#define SMEM_GEMM   (1024 + 2 * STAGE_BYTES)

#if HAS_TCGEN05
__device__ __forceinline__ void stage_load(uint32_t smem_base, int s, int kt,
                                           const __nv_bfloat16* __restrict__ Ah,
                                           const __nv_bfloat16* __restrict__ Al,
                                           const __nv_bfloat16* __restrict__ Bh,
                                           const __nv_bfloat16* __restrict__ Bl,
                                           int m0, int n0, int K, int ptid)
{
    const uint32_t sb = smem_base + 1024 + s * STAGE_BYTES;
    const int r = ptid;                         // 0..127
    {
        const size_t ka = (size_t)(m0 + r) * K + (size_t)kt * 64;
        const __nv_bfloat16* pah = Ah + ka;
        const __nv_bfloat16* pal = Al + ka;
        #pragma unroll
        for (int c = 0; c < 8; c++) {
            const uint32_t so = sw128((uint32_t)(r * 128 + c * 16));
            cp16(sb + so,         pah + c * 8);
            cp16(sb + 16384 + so, pal + c * 8);
        }
    }
    #pragma unroll
    for (int h = 0; h < 2; h++) {
        const int rr = r + h * 128;
        const size_t kb = (size_t)(n0 + rr) * K + (size_t)kt * 64;
        const __nv_bfloat16* pbh = Bh + kb;
        const __nv_bfloat16* pbl = Bl + kb;
        #pragma unroll
        for (int c = 0; c < 8; c++) {
            const uint32_t so = sw128((uint32_t)(rr * 128 + c * 16));
            cp16(sb + 32768 + so, pbh + c * 8);
            cp16(sb + 65536 + so, pbl + c * 8);
        }
    }
}
#endif

template <int EPI>
__global__ __launch_bounds__(256, 1)
void gemm_tc(const __nv_bfloat16* __restrict__ Ah, const __nv_bfloat16* __restrict__ Al,
             const __nv_bfloat16* __restrict__ Bh, const __nv_bfloat16* __restrict__ Bl,
             const float* __restrict__ bias, const float* __restrict__ resid,
             float* __restrict__ Cf,
             __nv_bfloat16* __restrict__ Chi, __nv_bfloat16* __restrict__ Clo,
             int N, int K)
{
#if HAS_TCGEN05
    extern __shared__ char smem[];
    const uint32_t sm = smem_u32_of(smem);
    const int tid = threadIdx.x;
    const int wid = tid >> 5;
    const int lid = tid & 31;
    const int m0 = blockIdx.y * 128;
    const int n0 = blockIdx.x * 256;
    const int T  = K >> 6;                 // K / 64

    if (tid == 0) {
        mbar_init(sm + 8,  1);   mbar_init(sm + 16, 1);
        mbar_init(sm + 32, 128); mbar_init(sm + 40, 128);
        mbar_init(sm + 56, 1);
    }
    if (wid == 0) {
        TC_ALLOC(sm, 256);
        TC_RELINQ();
    }
    __syncthreads();

    uint32_t tmem;
    asm volatile("ld.shared.b32 %0, [%1];" : "=r"(tmem) : "r"(sm));

    if (wid >= 4) {
        const int ptid = tid - 128;
        for (int t = 0; t < T; ++t) {
            const int s = t & 1;
            if (t >= 2) mbar_wait(sm + 8 + s * 8, ((t >> 1) - 1) & 1);
            stage_load(sm, s, t, Ah, Al, Bh, Bl, m0, n0, K, ptid);
            cp_async_arrive(sm + 32 + s * 8);
        }
    } else if (tid == 0) {
        uint64_t dAh[2], dAl[2], dBh[2], dBl[2];
        #pragma unroll
        for (int s = 0; s < 2; s++) {
            const uint32_t sb = sm + 1024 + s * STAGE_BYTES;
            dAh[s] = smem_desc(sb);
            dAl[s] = smem_desc(sb + 16384);
            dBh[s] = smem_desc(sb + 32768);
            dBl[s] = smem_desc(sb + 65536);
        }
        for (int t = 0; t < T; ++t) {
            const int s = t & 1;
            mbar_wait(sm + 32 + s * 8, (t >> 1) & 1);
            FENCE_ASYNC();
            #pragma unroll
            for (int ks = 0; ks < 4; ks++) {
                mma_f16_ss(tmem, dAh[s] + ks*2, dBh[s] + ks*2, GEMM_IDESC, !(t == 0 && ks == 0));
                mma_f16_ss(tmem, dAh[s] + ks*2, dBl[s] + ks*2, GEMM_IDESC, true);
                mma_f16_ss(tmem, dAl[s] + ks*2, dBh[s] + ks*2, GEMM_IDESC, true);
            }
            TC_COMMIT(sm + 8 + s * 8);
        }
        TC_COMMIT(sm + 56);
    }

    mbar_wait(sm + 56, 0);
    TC_FENCE_AFTER();

    const int m = m0 + (wid & 3) * 32 + lid;
    const int cb0 = (wid >> 2) * 4;
    #pragma unroll
    for (int cc = 0; cc < 4; cc++) {
        const int cb = cb0 + cc;
        uint32_t dr[32];
        TC_LD_X32(dr, tmem + cb * 32);
        TC_WAIT_LD();
        const int nb = n0 + cb * 32;
        if (EPI == EPI_GELU_SPLIT) {
            #pragma unroll
            for (int j = 0; j < 32; j += 4) {
                float4 v;
                v.x = gelu_tanh(__uint_as_float(dr[j])     + bias[nb + j]);
                v.y = gelu_tanh(__uint_as_float(dr[j + 1]) + bias[nb + j + 1]);
                v.z = gelu_tanh(__uint_as_float(dr[j + 2]) + bias[nb + j + 2]);
                v.w = gelu_tanh(__uint_as_float(dr[j + 3]) + bias[nb + j + 3]);
                split_store4(Chi, Clo, (size_t)m * N + nb + j, v);
            }
        } else {
            #pragma unroll
            for (int j = 0; j < 32; j += 4) {
                float4 v;
                v.x = __uint_as_float(dr[j])     + bias[nb + j];
                v.y = __uint_as_float(dr[j + 1]) + bias[nb + j + 1];
                v.z = __uint_as_float(dr[j + 2]) + bias[nb + j + 2];
                v.w = __uint_as_float(dr[j + 3]) + bias[nb + j + 3];
                if (EPI == EPI_BIAS_RES) {
                    const float4 rr = *(const float4*)(resid + (size_t)m * N + nb + j);
                    v.x += rr.x; v.y += rr.y; v.z += rr.z; v.w += rr.w;
                }
                *(float4*)(Cf + (size_t)m * N + nb + j) = v;
            }
        }
    }
    TC_FENCE_BEFORE();
    __syncthreads();
    if (wid == 0) TC_DEALLOC(tmem, 256);

#else  // ------------------- portable SIMT fallback (256 threads) ----------
    extern __shared__ char smem[];
    float* As = (float*)smem;
    float* Bs = (float*)(smem + 16 * 128 * 4);
    const int tid = threadIdx.x;
    const int m0 = blockIdx.y * 128;
    const int ty = tid >> 4;
    const int tx = tid & 15;

    for (int nh = 0; nh < 2; nh++) {
        const int n0 = blockIdx.x * 256 + nh * 128;
        float acc[8][8];
        #pragma unroll
        for (int i = 0; i < 8; i++)
            #pragma unroll
            for (int j = 0; j < 8; j++) acc[i][j] = 0.f;

        for (int k0 = 0; k0 < K; k0 += 16) {
            __syncthreads();
            #pragma unroll 4
            for (int i = tid; i < 2048; i += 256) {
                const int r = i >> 4, c = i & 15;
                const size_t gia = (size_t)(m0 + r) * K + k0 + c;
                As[c * 128 + r] = __bfloat162float(Ah[gia]) + __bfloat162float(Al[gia]);
                const size_t gib = (size_t)(n0 + r) * K + k0 + c;
                Bs[c * 128 + r] = __bfloat162float(Bh[gib]) + __bfloat162float(Bl[gib]);
            }
            __syncthreads();
            #pragma unroll
            for (int kk = 0; kk < 16; kk++) {
                float a[8], b[8];
                #pragma unroll
                for (int i = 0; i < 8; i++) a[i] = As[kk * 128 + ty * 8 + i];
                #pragma unroll
                for (int j = 0; j < 8; j++) b[j] = Bs[kk * 128 + tx * 8 + j];
                #pragma unroll
                for (int i = 0; i < 8; i++)
                    #pragma unroll
                    for (int j = 0; j < 8; j++)
                        acc[i][j] = fmaf(a[i], b[j], acc[i][j]);
            }
        }

        #pragma unroll
        for (int i = 0; i < 8; i++) {
            const int m = m0 + ty * 8 + i;
            #pragma unroll
            for (int j = 0; j < 8; j++) {
                const int n = n0 + tx * 8 + j;
                float v = acc[i][j] + bias[n];
                if (EPI == EPI_GELU_SPLIT) {
                    v = gelu_tanh(v);
                    __nv_bfloat16 hv = __float2bfloat16(v);
                    Chi[(size_t)m * N + n] = hv;
                    Clo[(size_t)m * N + n] = __float2bfloat16(v - __bfloat162float(hv));
                } else {
                    if (EPI == EPI_BIAS_RES) v += resid[(size_t)m * N + n];
                    Cf[(size_t)m * N + n] = v;
                }
            }
        }
        __syncthreads();
    }
#endif
}

// ---------------------------------------------------------------------------
// Causal flash attention: 128 queries/block (128 threads, 1 query row each),
// 64-key K/V tiles in smem, packed f32x2 FMA inner loops (2x fp32 throughput).
// Output written as bf16 (hi, lo) split.
// ---------------------------------------------------------------------------
__global__ __launch_bounds__(128)
void attn_kernel(const float* __restrict__ qkv,
                 __nv_bfloat16* __restrict__ out_hi,
                 __nv_bfloat16* __restrict__ out_lo)
{
    __shared__ float k_s[64][68];
    __shared__ float v_s[64][64];

    const int qt = blockIdx.x;              // 0..7 (128-query tiles)
    const int bh = blockIdx.y;
    const int b  = bh >> 4;
    const int h  = bh & 15;
    const int t  = threadIdx.x;             // 0..127
    const int g  = qt * 128 + t;            // global query row

    const size_t seq_base = (size_t)b * S_ * (3 * D_);
    const size_t head_off = (size_t)h * DH_;
    const int numkt = 2 * qt + 2;           // 64-key tiles to process

#if HAS_TCGEN05
    // ---- packed f32x2 path ----
    uint64_t qp[32];
    {
        const ulonglong2* q128 = (const ulonglong2*)(qkv + seq_base + head_off +
                                                     (size_t)g * (3 * D_));
        #pragma unroll
        for (int i = 0; i < 16; i++) {
            const ulonglong2 u = q128[i];
            qp[2*i] = u.x; qp[2*i+1] = u.y;
        }
    }
    uint64_t op[32];
    #pragma unroll
    for (int i = 0; i < 32; i++) op[i] = 0ull;   // (0.0f,0.0f)
    float m = -1e30f, l = 0.f;

    for (int kt = 0; kt < numkt; kt++) {
        const float* kp = qkv + seq_base + D_     + head_off + (size_t)(kt * 64) * (3 * D_);
        const float* vp = qkv + seq_base + 2 * D_ + head_off + (size_t)(kt * 64) * (3 * D_);
        #pragma unroll 4
        for (int i = t; i < 64 * 16; i += 128) {
            const int r = i >> 4;
            const int c = (i & 15) << 2;
            *(float4*)&k_s[r][c] = *(const float4*)(kp + (size_t)r * (3 * D_) + c);
            *(float4*)&v_s[r][c] = *(const float4*)(vp + (size_t)r * (3 * D_) + c);
        }
        __syncthreads();

        const bool edge = (kt >= 2 * qt);    // masking only in last two tiles
        #pragma unroll
        for (int half = 0; half < 2; half++) {
            const int kbase = half * 32;
            float s[32];
            float mt = -1e30f;
            #pragma unroll 2
            for (int kc = 0; kc < 32; kc++) {
                const ulonglong2* krow = (const ulonglong2*)k_s[kbase + kc];
                uint64_t a0 = 0ull, a1 = 0ull, a2 = 0ull, a3 = 0ull;
                #pragma unroll
                for (int i = 0; i < 8; i++) {
                    const ulonglong2 u0 = krow[2*i];
                    const ulonglong2 u1 = krow[2*i+1];
                    ffma2(a0, qp[4*i],   u0.x);
                    ffma2(a1, qp[4*i+1], u0.y);
                    ffma2(a2, qp[4*i+2], u1.x);
                    ffma2(a3, qp[4*i+3], u1.y);
                }
                fadd2(a0, a2); fadd2(a1, a3); fadd2(a0, a1);
                float lo, hi; unpack2f(a0, lo, hi);
                float sc = (lo + hi) * 0.125f;             // 1/sqrt(64)
                if (edge && (kt * 64 + kbase + kc) > g) sc = -1e30f;
                s[kc] = sc;
                mt = fmaxf(mt, sc);
            }
            const float m_new = fmaxf(m, mt);
            const float corr  = __expf(m - m_new);
            l *= corr;
            const uint64_t corr2 = pack2f(corr, corr);
            #pragma unroll
            for (int i = 0; i < 32; i++) fmul2(op[i], corr2);
            #pragma unroll 2
            for (int kc = 0; kc < 32; kc++) {
                const float p = __expf(s[kc] - m_new);
                l += p;
                const uint64_t p2 = pack2f(p, p);
                const ulonglong2* vrow = (const ulonglong2*)v_s[kbase + kc];
                #pragma unroll
                for (int i = 0; i < 16; i++) {
                    const ulonglong2 u = vrow[i];
                    ffma2(op[2*i],   p2, u.x);
                    ffma2(op[2*i+1], p2, u.y);
                }
            }
            m = m_new;
        }
        __syncthreads();
    }

    const float inv_l = 1.0f / l;
    const size_t out_base = ((size_t)b * S_ + g) * D_ + head_off;
    #pragma unroll
    for (int i = 0; i < 16; i++) {
        float4 v;
        unpack2f(op[2*i],   v.x, v.y);
        unpack2f(op[2*i+1], v.z, v.w);
        v.x *= inv_l; v.y *= inv_l; v.z *= inv_l; v.w *= inv_l;
        split_store4(out_hi, out_lo, out_base + i * 4, v);
    }

#else
    // ---- scalar fallback (same structure) ----
    float q[64];
    {
        const float* qpt = qkv + seq_base + head_off + (size_t)g * (3 * D_);
        #pragma unroll
        for (int d = 0; d < 64; d += 4) {
            const float4 u = *(const float4*)(qpt + d);
            q[d] = u.x; q[d+1] = u.y; q[d+2] = u.z; q[d+3] = u.w;
        }
    }
    float o[64];
    #pragma unroll
    for (int d = 0; d < 64; d++) o[d] = 0.f;
    float m = -1e30f, l = 0.f;

    for (int kt = 0; kt < numkt; kt++) {
        const float* kp = qkv + seq_base + D_     + head_off + (size_t)(kt * 64) * (3 * D_);
        const float* vp = qkv + seq_base + 2 * D_ + head_off + (size_t)(kt * 64) * (3 * D_);
        #pragma unroll 4
        for (int i = t; i < 64 * 16; i += 128) {
            const int r = i >> 4;
            const int c = (i & 15) << 2;
            *(float4*)&k_s[r][c] = *(const float4*)(kp + (size_t)r * (3 * D_) + c);
            *(float4*)&v_s[r][c] = *(const float4*)(vp + (size_t)r * (3 * D_) + c);
        }
        __syncthreads();

        const bool edge = (kt >= 2 * qt);
        #pragma unroll
        for (int half = 0; half < 2; half++) {
            const int kbase = half * 32;
            float s[32];
            float mt = -1e30f;
            #pragma unroll 2
            for (int kc = 0; kc < 32; kc++) {
                const float4* krow = (const float4*)k_s[kbase + kc];
                float d0 = 0.f, d1 = 0.f, d2 = 0.f, d3 = 0.f;
                #pragma unroll
                for (int d4 = 0; d4 < 16; d4++) {
                    const float4 kv = krow[d4];
                    d0 = fmaf(q[4*d4+0], kv.x, d0);
                    d1 = fmaf(q[4*d4+1], kv.y, d1);
                    d2 = fmaf(q[4*d4+2], kv.z, d2);
                    d3 = fmaf(q[4*d4+3], kv.w, d3);
                }
                float sc = (d0 + d1 + d2 + d3) * 0.125f;
                if (edge && (kt * 64 + kbase + kc) > g) sc = -1e30f;
                s[kc] = sc;
                mt = fmaxf(mt, sc);
            }
            const float m_new = fmaxf(m, mt);
            const float corr  = __expf(m - m_new);
            l *= corr;
            #pragma unroll
            for (int d = 0; d < 64; d++) o[d] *= corr;
            #pragma unroll 2
            for (int kc = 0; kc < 32; kc++) {
                const float p = __expf(s[kc] - m_new);
                l += p;
                const float4* vrow = (const float4*)v_s[kbase + kc];
                #pragma unroll
                for (int d4 = 0; d4 < 16; d4++) {
                    const float4 vv = vrow[d4];
                    o[4*d4+0] = fmaf(p, vv.x, o[4*d4+0]);
                    o[4*d4+1] = fmaf(p, vv.y, o[4*d4+1]);
                    o[4*d4+2] = fmaf(p, vv.z, o[4*d4+2]);
                    o[4*d4+3] = fmaf(p, vv.w, o[4*d4+3]);
                }
            }
            m = m_new;
        }
        __syncthreads();
    }

    const float inv_l = 1.0f / l;
    const size_t out_base = ((size_t)b * S_ + g) * D_ + head_off;
    #pragma unroll
    for (int d4 = 0; d4 < 16; d4++) {
        float4 v;
        v.x = o[4*d4+0] * inv_l;
        v.y = o[4*d4+1] * inv_l;
        v.z = o[4*d4+2] * inv_l;
        v.w = o[4*d4+3] * inv_l;
        split_store4(out_hi, out_lo, out_base + d4 * 4, v);
    }
#endif
}

// ---------------------------------------------------------------------------
// Launch
// ---------------------------------------------------------------------------
extern "C" void kernel_launch(void* const* d_in, const int* in_sizes, int n_in,
                              void* d_out, int out_size)
{
    const float* x     = (const float*)d_in[0];
    const float* ln1_g = (const float*)d_in[1];
    const float* ln1_b = (const float*)d_in[2];
    const float* w_qkv = (const float*)d_in[3];
    const float* b_qkv = (const float*)d_in[4];
    const float* w_o   = (const float*)d_in[5];
    const float* b_o   = (const float*)d_in[6];
    const float* ln2_g = (const float*)d_in[7];
    const float* ln2_b = (const float*)d_in[8];
    const float* w1    = (const float*)d_in[9];
    const float* b1    = (const float*)d_in[10];
    const float* w2    = (const float*)d_in[11];
    const float* b2    = (const float*)d_in[12];
    float* out = (float*)d_out;

    static bool inited = false;
    static float *p_qkv, *p_x2;
    static __nv_bfloat16 *p_act_h, *p_act_l, *p_big_h, *p_big_l;
    static __nv_bfloat16 *p_wqkv_h, *p_wqkv_l, *p_wo_h, *p_wo_l;
    static __nv_bfloat16 *p_w1_h, *p_w1_l, *p_w2_h, *p_w2_l;
    if (!inited) {
        void* p;
        cudaGetSymbolAddress(&p, g_qkv);    p_qkv    = (float*)p;
        cudaGetSymbolAddress(&p, g_x2);     p_x2     = (float*)p;
        cudaGetSymbolAddress(&p, g_act_hi); p_act_h  = (__nv_bfloat16*)p;
        cudaGetSymbolAddress(&p, g_act_lo); p_act_l  = (__nv_bfloat16*)p;
        cudaGetSymbolAddress(&p, g_big_hi); p_big_h  = (__nv_bfloat16*)p;
        cudaGetSymbolAddress(&p, g_big_lo); p_big_l  = (__nv_bfloat16*)p;
        cudaGetSymbolAddress(&p, g_wqkv_h); p_wqkv_h = (__nv_bfloat16*)p;
        cudaGetSymbolAddress(&p, g_wqkv_l); p_wqkv_l = (__nv_bfloat16*)p;
        cudaGetSymbolAddress(&p, g_wo_h);   p_wo_h   = (__nv_bfloat16*)p;
        cudaGetSymbolAddress(&p, g_wo_l);   p_wo_l   = (__nv_bfloat16*)p;
        cudaGetSymbolAddress(&p, g_w1_h);   p_w1_h   = (__nv_bfloat16*)p;
        cudaGetSymbolAddress(&p, g_w1_l);   p_w1_l   = (__nv_bfloat16*)p;
        cudaGetSymbolAddress(&p, g_w2_h);   p_w2_h   = (__nv_bfloat16*)p;
        cudaGetSymbolAddress(&p, g_w2_l);   p_w2_l   = (__nv_bfloat16*)p;
        cudaFuncSetAttribute(gemm_tc<EPI_BIAS>,       cudaFuncAttributeMaxDynamicSharedMemorySize, SMEM_GEMM);
        cudaFuncSetAttribute(gemm_tc<EPI_BIAS_RES>,   cudaFuncAttributeMaxDynamicSharedMemorySize, SMEM_GEMM);
        cudaFuncSetAttribute(gemm_tc<EPI_GELU_SPLIT>, cudaFuncAttributeMaxDynamicSharedMemorySize, SMEM_GEMM);
        inited = true;
    }

    // 0. weight splits
    split_kernel<<<(3*D_*D_/4 + 255)/256, 256>>>(w_qkv, p_wqkv_h, p_wqkv_l, 3*D_*D_/4);
    split_kernel<<<(D_*D_/4   + 255)/256, 256>>>(w_o,   p_wo_h,   p_wo_l,   D_*D_/4);
    split_kernel<<<(FF_*D_/4  + 255)/256, 256>>>(w1,    p_w1_h,   p_w1_l,   FF_*D_/4);
    split_kernel<<<(D_*FF_/4  + 255)/256, 256>>>(w2,    p_w2_h,   p_w2_l,   D_*FF_/4);

    // 1. LN1 + split
    ln_split_kernel<<<TOK, 256>>>(x, ln1_g, ln1_b, p_act_h, p_act_l);

    // 2. QKV projection
    gemm_tc<EPI_BIAS><<<dim3(3*D_/256, TOK/128), 256, SMEM_GEMM>>>(
        p_act_h, p_act_l, p_wqkv_h, p_wqkv_l, b_qkv, nullptr,
        p_qkv, nullptr, nullptr, 3*D_, D_);

    // 3. causal attention (128 queries per block)
    attn_kernel<<<dim3(S_/128, B_*H_), 128>>>(p_qkv, p_act_h, p_act_l);

    // 4. output projection + residual
    gemm_tc<EPI_BIAS_RES><<<dim3(D_/256, TOK/128), 256, SMEM_GEMM>>>(
        p_act_h, p_act_l, p_wo_h, p_wo_l, b_o, x,
        p_x2, nullptr, nullptr, D_, D_);

    // 5. LN2 + split
    ln_split_kernel<<<TOK, 256>>>(p_x2, ln2_g, ln2_b, p_act_h, p_act_l);

    // 6. FFN up + GELU + split
    gemm_tc<EPI_GELU_SPLIT><<<dim3(FF_/256, TOK/128), 256, SMEM_GEMM>>>(
        p_act_h, p_act_l, p_w1_h, p_w1_l, b1, nullptr,
        nullptr, p_big_h, p_big_l, FF_, D_);

    // 7. FFN down + residual -> out
    gemm_tc<EPI_BIAS_RES><<<dim3(D_/256, TOK/128), 256, SMEM_GEMM>>>(
        p_big_h, p_big_l, p_w2_h, p_w2_l, b2, p_x2,
        out, nullptr, nullptr, D_, FF_);
}

// round 8
// speedup vs baseline: 3.8019x; 1.4984x over previous
#include <cuda_runtime.h>
#include <cuda_bf16.h>
#include <math.h>
#include <stdint.h>

// ---------------------------------------------------------------------------
// Per-compilation-pass feature detection (plain compute_103 pass gets fallback)
// ---------------------------------------------------------------------------
#if defined(__CUDA_ARCH__)
# if defined(__CUDA_ARCH_FEAT_SM103_ALL) || defined(__CUDA_ARCH_FEAT_SM100_ALL) || \
     (defined(__CUDA_ARCH_FAMILY_SPECIFIC__) && (__CUDA_ARCH_FAMILY_SPECIFIC__ >= 1000))
#  define HAS_TCGEN05 1
# else
#  define HAS_TCGEN05 0
# endif
#else
# define HAS_TCGEN05 0
#endif

// ---------------------------------------------------------------------------
// Problem constants
// ---------------------------------------------------------------------------
#define B_    8
#define S_    1024
#define D_    1024
#define H_    16
#define DH_   64
#define FF_   4096
#define TOK   (B_ * S_)

// ---------------------------------------------------------------------------
// Scratch. bf16 operand buffers are stored TILED: 16KB tiles of 128 rows x
// 64 cols (128B rows) with the SW128 swizzle pre-applied, tile index
// (row>>7)*(K>>6) + (col>>6). TMA bulk copies move whole tiles into SMEM.
// ---------------------------------------------------------------------------
__device__ float g_qkv[(size_t)TOK * 3 * D_];
__device__ float g_x2 [(size_t)TOK * D_];
__device__ __align__(1024) __nv_bfloat16 g_act_hi[(size_t)TOK * D_];
__device__ __align__(1024) __nv_bfloat16 g_act_lo[(size_t)TOK * D_];
__device__ __align__(1024) __nv_bfloat16 g_big_hi[(size_t)TOK * FF_];
__device__ __align__(1024) __nv_bfloat16 g_big_lo[(size_t)TOK * FF_];
__device__ __align__(1024) __nv_bfloat16 g_wqkv_h[(size_t)3 * D_ * D_];
__device__ __align__(1024) __nv_bfloat16 g_wqkv_l[(size_t)3 * D_ * D_];
__device__ __align__(1024) __nv_bfloat16 g_wo_h[(size_t)D_ * D_];
__device__ __align__(1024) __nv_bfloat16 g_wo_l[(size_t)D_ * D_];
__device__ __align__(1024) __nv_bfloat16 g_w1_h[(size_t)FF_ * D_];
__device__ __align__(1024) __nv_bfloat16 g_w1_l[(size_t)FF_ * D_];
__device__ __align__(1024) __nv_bfloat16 g_w2_h[(size_t)D_ * FF_];
__device__ __align__(1024) __nv_bfloat16 g_w2_l[(size_t)D_ * FF_];

// ---------------------------------------------------------------------------
// Tiled-layout addressing (portable)
// ---------------------------------------------------------------------------
__device__ __forceinline__ uint32_t sw128(uint32_t off) { return off ^ ((off >> 3) & 0x70); }

// byte offset of element (row, col) in a tiled+swizzled bf16 buffer of width Kk
__device__ __forceinline__ size_t tiled_off(int row, int col, int Kk) {
    const int tr = row >> 7, tk = col >> 6;
    const uint32_t inb = ((uint32_t)(row & 127) << 7) | ((uint32_t)(col & 63) << 1);
    return (((size_t)tr * (size_t)(Kk >> 6) + (size_t)tk) << 14) + sw128(inb);
}

// ---------------------------------------------------------------------------
// PTX helpers
// ---------------------------------------------------------------------------
#if HAS_TCGEN05
__device__ __forceinline__ uint32_t smem_u32_of(const void* p) {
    uint32_t a;
    asm("{ .reg .u64 t; cvta.to.shared.u64 t, %1; cvt.u32.u64 %0, t; }" : "=r"(a) : "l"(p));
    return a;
}
__device__ __forceinline__ void tma_bulk(uint32_t dst, const void* src, uint32_t bytes,
                                         uint32_t mbar) {
    asm volatile(
        "cp.async.bulk.shared::cta.global.mbarrier::complete_tx::bytes [%0], [%1], %2, [%3];"
        :: "r"(dst), "l"(src), "r"(bytes), "r"(mbar) : "memory");
}
__device__ __forceinline__ void mbar_expect_tx(uint32_t mbar, uint32_t bytes) {
    asm volatile("mbarrier.arrive.expect_tx.shared.b64 _, [%0], %1;"
                 :: "r"(mbar), "r"(bytes) : "memory");
}

__device__ __forceinline__ uint64_t smem_desc(uint32_t addr) {
    constexpr uint64_t BASE = (uint64_t(2) << 61)   // SW128
                            | (uint64_t(1) << 46)   // Blackwell
                            | (uint64_t(64) << 32)  // SBO = 64
                            | (uint64_t(1) << 16);  // LBO = 1
    return BASE | ((uint64_t)(addr >> 4) & 0x3FFF);
}
// idesc: kind::f16, d=f32, a=bf16, b=bf16, M=128, N=256
#define GEMM_IDESC ((1u<<4) | (1u<<7) | (1u<<10) | ((256u/8)<<17) | ((128u/16)<<24))

__device__ __forceinline__ void mma_f16_ss(uint32_t d, uint64_t a, uint64_t b,
                                           uint32_t idesc, bool acc) {
    uint32_t e = acc ? 1u : 0u;
    asm volatile(
        "{\n\t.reg .pred p;\n\t"
        "setp.ne.u32 p, %4, 0;\n\t"
        "tcgen05.mma.cta_group::1.kind::f16 [%0], %1, %2, %3, {%5, %5, %5, %5}, p;\n\t}"
        :: "r"(d), "l"(a), "l"(b), "r"(idesc), "r"(e), "r"(0u) : "memory");
}
__device__ __forceinline__ void mbar_init(uint32_t addr, uint32_t cnt) {
    asm volatile("mbarrier.init.shared.b64 [%0], %1;" :: "r"(addr), "r"(cnt) : "memory");
}
__device__ __forceinline__ void mbar_wait(uint32_t addr, uint32_t parity) {
    asm volatile(
        "{\n\t.reg .pred P;\n\t"
        "W%=:\n\t"
        "mbarrier.try_wait.parity.acquire.cta.shared::cta.b64 P, [%0], %1, 0x989680;\n\t"
        "@!P bra W%=;\n\t}"
        :: "r"(addr), "r"(parity) : "memory");
}

#define TC_ALLOC(sm, n)   asm volatile("tcgen05.alloc.cta_group::1.sync.aligned.shared::cta.b32 [%0], %1;" :: "r"(sm), "r"(n) : "memory")
#define TC_RELINQ()       asm volatile("tcgen05.relinquish_alloc_permit.cta_group::1.sync.aligned;")
#define TC_DEALLOC(t, n)  asm volatile("tcgen05.dealloc.cta_group::1.sync.aligned.b32 %0, %1;" :: "r"(t), "r"(n))
#define TC_COMMIT(mb)     asm volatile("tcgen05.commit.cta_group::1.mbarrier::arrive::one.shared::cluster.b64 [%0];" :: "r"(mb) : "memory")
#define TC_FENCE_AFTER()  asm volatile("tcgen05.fence::after_thread_sync;" ::: "memory")
#define TC_FENCE_BEFORE() asm volatile("tcgen05.fence::before_thread_sync;" ::: "memory")
#define TC_WAIT_LD()      asm volatile("tcgen05.wait::ld.sync.aligned;" ::: "memory")

#define TC_LD_X32(r, t) \
    asm volatile( \
        "tcgen05.ld.sync.aligned.32x32b.x32.b32 " \
        "{%0, %1, %2, %3, %4, %5, %6, %7, " \
        " %8, %9, %10, %11, %12, %13, %14, %15, " \
        " %16, %17, %18, %19, %20, %21, %22, %23, " \
        " %24, %25, %26, %27, %28, %29, %30, %31}, [%32];" \
        : "=r"((r)[0]),  "=r"((r)[1]),  "=r"((r)[2]),  "=r"((r)[3]), \
          "=r"((r)[4]),  "=r"((r)[5]),  "=r"((r)[6]),  "=r"((r)[7]), \
          "=r"((r)[8]),  "=r"((r)[9]),  "=r"((r)[10]), "=r"((r)[11]), \
          "=r"((r)[12]), "=r"((r)[13]), "=r"((r)[14]), "=r"((r)[15]), \
          "=r"((r)[16]), "=r"((r)[17]), "=r"((r)[18]), "=r"((r)[19]), \
          "=r"((r)[20]), "=r"((r)[21]), "=r"((r)[22]), "=r"((r)[23]), \
          "=r"((r)[24]), "=r"((r)[25]), "=r"((r)[26]), "=r"((r)[27]), \
          "=r"((r)[28]), "=r"((r)[29]), "=r"((r)[30]), "=r"((r)[31]) \
        : "r"(t))

// ---- packed f32x2 (Blackwell) ----
__device__ __forceinline__ uint64_t pack2f(float lo, float hi) {
    uint64_t r;
    asm("mov.b64 %0, {%1, %2};" : "=l"(r) : "f"(lo), "f"(hi));
    return r;
}
__device__ __forceinline__ void unpack2f(uint64_t v, float& lo, float& hi) {
    asm("mov.b64 {%0, %1}, %2;" : "=f"(lo), "=f"(hi) : "l"(v));
}
__device__ __forceinline__ void ffma2(uint64_t& d, uint64_t a, uint64_t b) {
    asm("fma.rn.f32x2 %0, %1, %2, %3;" : "=l"(d) : "l"(a), "l"(b), "l"(d));
}
__device__ __forceinline__ void fadd2(uint64_t& d, uint64_t a) {
    asm("add.rn.f32x2 %0, %1, %2;" : "=l"(d) : "l"(d), "l"(a));
}
__device__ __forceinline__ void fmul2(uint64_t& d, uint64_t a) {
    asm("mul.rn.f32x2 %0, %1, %2;" : "=l"(d) : "l"(d), "l"(a));
}
#endif  // HAS_TCGEN05

// ---------------------------------------------------------------------------
// fp32 -> bf16 (hi, lo) split store into TILED buffers
// ---------------------------------------------------------------------------
__device__ __forceinline__ void split_store4_tiled(__nv_bfloat16* __restrict__ hi,
                                                   __nv_bfloat16* __restrict__ lo,
                                                   int row, int col, int Kk, float4 v) {
    const size_t off = tiled_off(row, col, Kk);
    __nv_bfloat16 h0 = __float2bfloat16(v.x);
    __nv_bfloat16 h1 = __float2bfloat16(v.y);
    __nv_bfloat16 h2 = __float2bfloat16(v.z);
    __nv_bfloat16 h3 = __float2bfloat16(v.w);
    __nv_bfloat16 l0 = __float2bfloat16(v.x - __bfloat162float(h0));
    __nv_bfloat16 l1 = __float2bfloat16(v.y - __bfloat162float(h1));
    __nv_bfloat16 l2 = __float2bfloat16(v.z - __bfloat162float(h2));
    __nv_bfloat16 l3 = __float2bfloat16(v.w - __bfloat162float(h3));
    __nv_bfloat162 ha; ha.x = h0; ha.y = h1;
    __nv_bfloat162 hb; hb.x = h2; hb.y = h3;
    __nv_bfloat162 la; la.x = l0; la.y = l1;
    __nv_bfloat162 lb; lb.x = l2; lb.y = l3;
    *(__nv_bfloat162*)((char*)hi + off)     = ha;
    *(__nv_bfloat162*)((char*)hi + off + 4) = hb;
    *(__nv_bfloat162*)((char*)lo + off)     = la;
    *(__nv_bfloat162*)((char*)lo + off + 4) = lb;
}

// Weight split: [N, K] row-major fp32 -> tiled bf16 hi/lo
__global__ __launch_bounds__(256)
void split_kernel(const float* __restrict__ x,
                  __nv_bfloat16* __restrict__ hi,
                  __nv_bfloat16* __restrict__ lo, int n4, int K)
{
    int i = blockIdx.x * 256 + threadIdx.x;
    if (i < n4) {
        float4 v = ((const float4*)x)[i];
        const int e = i << 2;
        split_store4_tiled(hi, lo, e / K, e % K, K, v);
    }
}

// ---------------------------------------------------------------------------
// LayerNorm fused with tiled bf16 split output
// ---------------------------------------------------------------------------
__global__ __launch_bounds__(256)
void ln_split_kernel(const float* __restrict__ x,
                     const float* __restrict__ gw,
                     const float* __restrict__ bw,
                     __nv_bfloat16* __restrict__ out_hi,
                     __nv_bfloat16* __restrict__ out_lo)
{
    __shared__ float red[16];
    const int row = blockIdx.x;
    const int tid = threadIdx.x;

    const float4 v = ((const float4*)(x + (size_t)row * D_))[tid];
    float s  = v.x + v.y + v.z + v.w;
    float ss = v.x*v.x + v.y*v.y + v.z*v.z + v.w*v.w;

    #pragma unroll
    for (int o = 16; o; o >>= 1) {
        s  += __shfl_xor_sync(0xffffffffu, s,  o);
        ss += __shfl_xor_sync(0xffffffffu, ss, o);
    }
    const int wid = tid >> 5, lid = tid & 31;
    if (lid == 0) { red[wid] = s; red[8 + wid] = ss; }
    __syncthreads();

    float sum = 0.f, sq = 0.f;
    #pragma unroll
    for (int i = 0; i < 8; i++) { sum += red[i]; sq += red[8 + i]; }

    const float mu  = sum * (1.0f / D_);
    const float var = sq  * (1.0f / D_) - mu * mu;
    const float rs  = rsqrtf(var + 1e-5f);

    const float4 g4 = ((const float4*)gw)[tid];
    const float4 b4 = ((const float4*)bw)[tid];
    float4 o;
    o.x = (v.x - mu) * rs * g4.x + b4.x;
    o.y = (v.y - mu) * rs * g4.y + b4.y;
    o.z = (v.z - mu) * rs * g4.z + b4.z;
    o.w = (v.w - mu) * rs * g4.w + b4.w;
    split_store4_tiled(out_hi, out_lo, row, tid * 4, D_, o);
}

// ---------------------------------------------------------------------------
// GEMM (TN), tcgen05 128x256 tile, TMA 1D bulk loads from pre-tiled gmem.
//   Thread 0: sole producer (expect_tx + 6x16KB bulk copies/stage) and MMA
//   issuer. 2 stages. full[s] (count 1, tx-tracked), done[s] (commit),
//   fin (single-phase). All 8 warps: epilogue.
// ---------------------------------------------------------------------------
enum { EPI_BIAS = 0, EPI_BIAS_RES = 1, EPI_GELU_SPLIT = 2 };

__device__ __forceinline__ float gelu_tanh(float x)
{
    const float u = 0.7978845608028654f * (x + 0.044715f * x * x * x);
    return 0.5f * x * (1.0f + tanhf(u));
}

#define STAGE_BYTES 98304
#define SMEM_GEMM   (1024 + 2 * STAGE_BYTES)

template <int EPI>
__global__ __launch_bounds__(256, 1)
void gemm_tc(const __nv_bfloat16* __restrict__ Ah, const __nv_bfloat16* __restrict__ Al,
             const __nv_bfloat16* __restrict__ Bh, const __nv_bfloat16* __restrict__ Bl,
             const float* __restrict__ bias, const float* __restrict__ resid,
             float* __restrict__ Cf,
             __nv_bfloat16* __restrict__ Chi, __nv_bfloat16* __restrict__ Clo,
             int N, int K)
{
#if HAS_TCGEN05
    extern __shared__ char smem[];
    const uint32_t sm = smem_u32_of(smem);
    const int tid = threadIdx.x;
    const int wid = tid >> 5;
    const int lid = tid & 31;
    const int mb  = blockIdx.y;            // 128-row A tile index
    const int nb0 = blockIdx.x * 2;        // first of two 128-row B tiles
    const int m0  = mb << 7;
    const int n0  = blockIdx.x << 8;
    const int KT  = K >> 6;
    const int T   = KT;

    if (tid == 0) {
        mbar_init(sm + 8,  1);  mbar_init(sm + 16, 1);   // done[s]
        mbar_init(sm + 32, 1);  mbar_init(sm + 40, 1);   // full[s] (tx-tracked)
        mbar_init(sm + 56, 1);                            // fin
    }
    if (wid == 0) {
        TC_ALLOC(sm, 256);
        TC_RELINQ();
    }
    __syncthreads();

    uint32_t tmem;
    asm volatile("ld.shared.b32 %0, [%1];" : "=r"(tmem) : "r"(sm));

    if (tid == 0) {
        const char* pAh = (const char*)Ah;
        const char* pAl = (const char*)Al;
        const char* pBh = (const char*)Bh;
        const char* pBl = (const char*)Bl;

        uint64_t dAh[2], dAl[2], dBh[2], dBl[2];
        #pragma unroll
        for (int s = 0; s < 2; s++) {
            const uint32_t sb = sm + 1024 + s * STAGE_BYTES;
            dAh[s] = smem_desc(sb);
            dAl[s] = smem_desc(sb + 16384);
            dBh[s] = smem_desc(sb + 32768);
            dBl[s] = smem_desc(sb + 65536);
        }

        // stage loader: 6 x 16KB tiles
        auto load_stage = [&](int s, int kt) {
            const uint32_t sb = sm + 1024 + s * STAGE_BYTES;
            const uint32_t fb = sm + 32 + s * 8;
            mbar_expect_tx(fb, STAGE_BYTES);
            const size_t aoff = ((size_t)(mb * KT + kt)) << 14;
            const size_t b0   = ((size_t)(nb0 * KT + kt)) << 14;
            const size_t b1   = ((size_t)((nb0 + 1) * KT + kt)) << 14;
            tma_bulk(sb,         pAh + aoff, 16384, fb);
            tma_bulk(sb + 16384, pAl + aoff, 16384, fb);
            tma_bulk(sb + 32768, pBh + b0,   16384, fb);
            tma_bulk(sb + 49152, pBh + b1,   16384, fb);
            tma_bulk(sb + 65536, pBl + b0,   16384, fb);
            tma_bulk(sb + 81920, pBl + b1,   16384, fb);
        };

        load_stage(0, 0);
        if (T > 1) load_stage(1, 1);

        for (int t = 0; t < T; ++t) {
            const int s = t & 1;
            mbar_wait(sm + 32 + s * 8, (t >> 1) & 1);
            #pragma unroll
            for (int ks = 0; ks < 4; ks++) {
                mma_f16_ss(tmem, dAh[s] + ks*2, dBh[s] + ks*2, GEMM_IDESC, !(t == 0 && ks == 0));
                mma_f16_ss(tmem, dAh[s] + ks*2, dBl[s] + ks*2, GEMM_IDESC, true);
                mma_f16_ss(tmem, dAl[s] + ks*2, dBh[s] + ks*2, GEMM_IDESC, true);
            }
            TC_COMMIT(sm + 8 + s * 8);
            if (t + 2 < T) {
                mbar_wait(sm + 8 + s * 8, (t >> 1) & 1);   // MMA(t) done -> recycle
                load_stage(s, t + 2);
            }
        }
        TC_COMMIT(sm + 56);   // single-phase completion of ALL issued MMAs
    }

    // ALL threads wait the single-phase fin barrier
    mbar_wait(sm + 56, 0);
    TC_FENCE_AFTER();

    // epilogue: warp w -> rows (w&3)*32+lid, column blocks (w>>2)*4 + {0..3}
    const int m = m0 + (wid & 3) * 32 + lid;
    const int cb0 = (wid >> 2) * 4;
    #pragma unroll
    for (int cc = 0; cc < 4; cc++) {
        const int cb = cb0 + cc;
        uint32_t dr[32];
        TC_LD_X32(dr, tmem + cb * 32);
        TC_WAIT_LD();
        const int nb = n0 + cb * 32;
        if (EPI == EPI_GELU_SPLIT) {
            #pragma unroll
            for (int j = 0; j < 32; j += 4) {
                float4 v;
                v.x = gelu_tanh(__uint_as_float(dr[j])     + bias[nb + j]);
                v.y = gelu_tanh(__uint_as_float(dr[j + 1]) + bias[nb + j + 1]);
                v.z = gelu_tanh(__uint_as_float(dr[j + 2]) + bias[nb + j + 2]);
                v.w = gelu_tanh(__uint_as_float(dr[j + 3]) + bias[nb + j + 3]);
                split_store4_tiled(Chi, Clo, m, nb + j, N, v);
            }
        } else {
            #pragma unroll
            for (int j = 0; j < 32; j += 4) {
                float4 v;
                v.x = __uint_as_float(dr[j])     + bias[nb + j];
                v.y = __uint_as_float(dr[j + 1]) + bias[nb + j + 1];
                v.z = __uint_as_float(dr[j + 2]) + bias[nb + j + 2];
                v.w = __uint_as_float(dr[j + 3]) + bias[nb + j + 3];
                if (EPI == EPI_BIAS_RES) {
                    const float4 rr = *(const float4*)(resid + (size_t)m * N + nb + j);
                    v.x += rr.x; v.y += rr.y; v.z += rr.z; v.w += rr.w;
                }
                *(float4*)(Cf + (size_t)m * N + nb + j) = v;
            }
        }
    }
    TC_FENCE_BEFORE();
    __syncthreads();
    if (wid == 0) TC_DEALLOC(tmem, 256);

#else  // ------------------- portable SIMT fallback (256 threads) ----------
    extern __shared__ char smem[];
    float* As = (float*)smem;
    float* Bs = (float*)(smem + 16 * 128 * 4);
    const int tid = threadIdx.x;
    const int m0 = blockIdx.y * 128;
    const int ty = tid >> 4;
    const int tx = tid & 15;

    for (int nh = 0; nh < 2; nh++) {
        const int n0 = blockIdx.x * 256 + nh * 128;
        float acc[8][8];
        #pragma unroll
        for (int i = 0; i < 8; i++)
            #pragma unroll
            for (int j = 0; j < 8; j++) acc[i][j] = 0.f;

        for (int k0 = 0; k0 < K; k0 += 16) {
            __syncthreads();
            #pragma unroll 4
            for (int i = tid; i < 2048; i += 256) {
                const int r = i >> 4, c = i & 15;
                const size_t oa = tiled_off(m0 + r, k0 + c, K);
                As[c * 128 + r] =
                    __bfloat162float(*(const __nv_bfloat16*)((const char*)Ah + oa)) +
                    __bfloat162float(*(const __nv_bfloat16*)((const char*)Al + oa));
                const size_t ob = tiled_off(n0 + r, k0 + c, K);
                Bs[c * 128 + r] =
                    __bfloat162float(*(const __nv_bfloat16*)((const char*)Bh + ob)) +
                    __bfloat162float(*(const __nv_bfloat16*)((const char*)Bl + ob));
            }
            __syncthreads();
            #pragma unroll
            for (int kk = 0; kk < 16; kk++) {
                float a[8], b[8];
                #pragma unroll
                for (int i = 0; i < 8; i++) a[i] = As[kk * 128 + ty * 8 + i];
                #pragma unroll
                for (int j = 0; j < 8; j++) b[j] = Bs[kk * 128 + tx * 8 + j];
                #pragma unroll
                for (int i = 0; i < 8; i++)
                    #pragma unroll
                    for (int j = 0; j < 8; j++)
                        acc[i][j] = fmaf(a[i], b[j], acc[i][j]);
            }
        }

        #pragma unroll
        for (int i = 0; i < 8; i++) {
            const int m = m0 + ty * 8 + i;
            #pragma unroll
            for (int j = 0; j < 8; j++) {
                const int n = n0 + tx * 8 + j;
                float v = acc[i][j] + bias[n];
                if (EPI == EPI_GELU_SPLIT) {
                    v = gelu_tanh(v);
                    __nv_bfloat16 hv = __float2bfloat16(v);
                    const size_t oc = tiled_off(m, n, N);
                    *(__nv_bfloat16*)((char*)Chi + oc) = hv;
                    *(__nv_bfloat16*)((char*)Clo + oc) =
                        __float2bfloat16(v - __bfloat162float(hv));
                } else {
                    if (EPI == EPI_BIAS_RES) v += resid[(size_t)m * N + n];
                    Cf[(size_t)m * N + n] = v;
                }
            }
        }
        __syncthreads();
    }
#endif
}

// ---------------------------------------------------------------------------
// Causal flash attention: 128 queries/block, 64-key K/V tiles in smem,
// packed f32x2 FMA inner loops. Output: tiled bf16 (hi, lo) split.
// ---------------------------------------------------------------------------
__global__ __launch_bounds__(128)
void attn_kernel(const float* __restrict__ qkv,
                 __nv_bfloat16* __restrict__ out_hi,
                 __nv_bfloat16* __restrict__ out_lo)
{
    __shared__ float k_s[64][68];
    __shared__ float v_s[64][64];

    const int qt = blockIdx.x;
    const int bh = blockIdx.y;
    const int b  = bh >> 4;
    const int h  = bh & 15;
    const int t  = threadIdx.x;
    const int g  = qt * 128 + t;

    const size_t seq_base = (size_t)b * S_ * (3 * D_);
    const size_t head_off = (size_t)h * DH_;
    const int numkt = 2 * qt + 2;
    const int orow = b * S_ + g;           // row in tiled act matrix

#if HAS_TCGEN05
    uint64_t qp[32];
    {
        const ulonglong2* q128 = (const ulonglong2*)(qkv + seq_base + head_off +
                                                     (size_t)g * (3 * D_));
        #pragma unroll
        for (int i = 0; i < 16; i++) {
            const ulonglong2 u = q128[i];
            qp[2*i] = u.x; qp[2*i+1] = u.y;
        }
    }
    uint64_t op[32];
    #pragma unroll
    for (int i = 0; i < 32; i++) op[i] = 0ull;
    float m = -1e30f, l = 0.f;

    for (int kt = 0; kt < numkt; kt++) {
        const float* kp = qkv + seq_base + D_     + head_off + (size_t)(kt * 64) * (3 * D_);
        const float* vp = qkv + seq_base + 2 * D_ + head_off + (size_t)(kt * 64) * (3 * D_);
        #pragma unroll 4
        for (int i = t; i < 64 * 16; i += 128) {
            const int r = i >> 4;
            const int c = (i & 15) << 2;
            *(float4*)&k_s[r][c] = *(const float4*)(kp + (size_t)r * (3 * D_) + c);
            *(float4*)&v_s[r][c] = *(const float4*)(vp + (size_t)r * (3 * D_) + c);
        }
        __syncthreads();

        const bool edge = (kt >= 2 * qt);
        #pragma unroll
        for (int half = 0; half < 2; half++) {
            const int kbase = half * 32;
            float s[32];
            float mt = -1e30f;
            #pragma unroll 2
            for (int kc = 0; kc < 32; kc++) {
                const ulonglong2* krow = (const ulonglong2*)k_s[kbase + kc];
                uint64_t a0 = 0ull, a1 = 0ull, a2 = 0ull, a3 = 0ull;
                #pragma unroll
                for (int i = 0; i < 8; i++) {
                    const ulonglong2 u0 = krow[2*i];
                    const ulonglong2 u1 = krow[2*i+1];
                    ffma2(a0, qp[4*i],   u0.x);
                    ffma2(a1, qp[4*i+1], u0.y);
                    ffma2(a2, qp[4*i+2], u1.x);
                    ffma2(a3, qp[4*i+3], u1.y);
                }
                fadd2(a0, a2); fadd2(a1, a3); fadd2(a0, a1);
                float lo, hi; unpack2f(a0, lo, hi);
                float sc = (lo + hi) * 0.125f;
                if (edge && (kt * 64 + kbase + kc) > g) sc = -1e30f;
                s[kc] = sc;
                mt = fmaxf(mt, sc);
            }
            const float m_new = fmaxf(m, mt);
            const float corr  = __expf(m - m_new);
            l *= corr;
            const uint64_t corr2 = pack2f(corr, corr);
            #pragma unroll
            for (int i = 0; i < 32; i++) fmul2(op[i], corr2);
            #pragma unroll 2
            for (int kc = 0; kc < 32; kc++) {
                const float p = __expf(s[kc] - m_new);
                l += p;
                const uint64_t p2 = pack2f(p, p);
                const ulonglong2* vrow = (const ulonglong2*)v_s[kbase + kc];
                #pragma unroll
                for (int i = 0; i < 16; i++) {
                    const ulonglong2 u = vrow[i];
                    ffma2(op[2*i],   p2, u.x);
                    ffma2(op[2*i+1], p2, u.y);
                }
            }
            m = m_new;
        }
        __syncthreads();
    }

    const float inv_l = 1.0f / l;
    #pragma unroll
    for (int i = 0; i < 16; i++) {
        float4 v;
        unpack2f(op[2*i],   v.x, v.y);
        unpack2f(op[2*i+1], v.z, v.w);
        v.x *= inv_l; v.y *= inv_l; v.z *= inv_l; v.w *= inv_l;
        split_store4_tiled(out_hi, out_lo, orow, (int)head_off + i * 4, D_, v);
    }

#else
    float q[64];
    {
        const float* qpt = qkv + seq_base + head_off + (size_t)g * (3 * D_);
        #pragma unroll
        for (int d = 0; d < 64; d += 4) {
            const float4 u = *(const float4*)(qpt + d);
            q[d] = u.x; q[d+1] = u.y; q[d+2] = u.z; q[d+3] = u.w;
        }
    }
    float o[64];
    #pragma unroll
    for (int d = 0; d < 64; d++) o[d] = 0.f;
    float m = -1e30f, l = 0.f;

    for (int kt = 0; kt < numkt; kt++) {
        const float* kp = qkv + seq_base + D_     + head_off + (size_t)(kt * 64) * (3 * D_);
        const float* vp = qkv + seq_base + 2 * D_ + head_off + (size_t)(kt * 64) * (3 * D_);
        #pragma unroll 4
        for (int i = t; i < 64 * 16; i += 128) {
            const int r = i >> 4;
            const int c = (i & 15) << 2;
            *(float4*)&k_s[r][c] = *(const float4*)(kp + (size_t)r * (3 * D_) + c);
            *(float4*)&v_s[r][c] = *(const float4*)(vp + (size_t)r * (3 * D_) + c);
        }
        __syncthreads();

        const bool edge = (kt >= 2 * qt);
        #pragma unroll
        for (int half = 0; half < 2; half++) {
            const int kbase = half * 32;
            float s[32];
            float mt = -1e30f;
            #pragma unroll 2
            for (int kc = 0; kc < 32; kc++) {
                const float4* krow = (const float4*)k_s[kbase + kc];
                float d0 = 0.f, d1 = 0.f, d2 = 0.f, d3 = 0.f;
                #pragma unroll
                for (int d4 = 0; d4 < 16; d4++) {
                    const float4 kv = krow[d4];
                    d0 = fmaf(q[4*d4+0], kv.x, d0);
                    d1 = fmaf(q[4*d4+1], kv.y, d1);
                    d2 = fmaf(q[4*d4+2], kv.z, d2);
                    d3 = fmaf(q[4*d4+3], kv.w, d3);
                }
                float sc = (d0 + d1 + d2 + d3) * 0.125f;
                if (edge && (kt * 64 + kbase + kc) > g) sc = -1e30f;
                s[kc] = sc;
                mt = fmaxf(mt, sc);
            }
            const float m_new = fmaxf(m, mt);
            const float corr  = __expf(m - m_new);
            l *= corr;
            #pragma unroll
            for (int d = 0; d < 64; d++) o[d] *= corr;
            #pragma unroll 2
            for (int kc = 0; kc < 32; kc++) {
                const float p = __expf(s[kc] - m_new);
                l += p;
                const float4* vrow = (const float4*)v_s[kbase + kc];
                #pragma unroll
                for (int d4 = 0; d4 < 16; d4++) {
                    const float4 vv = vrow[d4];
                    o[4*d4+0] = fmaf(p, vv.x, o[4*d4+0]);
                    o[4*d4+1] = fmaf(p, vv.y, o[4*d4+1]);
                    o[4*d4+2] = fmaf(p, vv.z, o[4*d4+2]);
                    o[4*d4+3] = fmaf(p, vv.w, o[4*d4+3]);
                }
            }
            m = m_new;
        }
        __syncthreads();
    }

    const float inv_l = 1.0f / l;
    #pragma unroll
    for (int d4 = 0; d4 < 16; d4++) {
        float4 v;
        v.x = o[4*d4+0] * inv_l;
        v.y = o[4*d4+1] * inv_l;
        v.z = o[4*d4+2] * inv_l;
        v.w = o[4*d4+3] * inv_l;
        split_store4_tiled(out_hi, out_lo, orow, (int)head_off + d4 * 4, D_, v);
    }
#endif
}

// ---------------------------------------------------------------------------
// Launch
// ---------------------------------------------------------------------------
extern "C" void kernel_launch(void* const* d_in, const int* in_sizes, int n_in,
                              void* d_out, int out_size)
{
    const float* x     = (const float*)d_in[0];
    const float* ln1_g = (const float*)d_in[1];
    const float* ln1_b = (const float*)d_in[2];
    const float* w_qkv = (const float*)d_in[3];
    const float* b_qkv = (const float*)d_in[4];
    const float* w_o   = (const float*)d_in[5];
    const float* b_o   = (const float*)d_in[6];
    const float* ln2_g = (const float*)d_in[7];
    const float* ln2_b = (const float*)d_in[8];
    const float* w1    = (const float*)d_in[9];
    const float* b1    = (const float*)d_in[10];
    const float* w2    = (const float*)d_in[11];
    const float* b2    = (const float*)d_in[12];
    float* out = (float*)d_out;

    static bool inited = false;
    static float *p_qkv, *p_x2;
    static __nv_bfloat16 *p_act_h, *p_act_l, *p_big_h, *p_big_l;
    static __nv_bfloat16 *p_wqkv_h, *p_wqkv_l, *p_wo_h, *p_wo_l;
    static __nv_bfloat16 *p_w1_h, *p_w1_l, *p_w2_h, *p_w2_l;
    if (!inited) {
        void* p;
        cudaGetSymbolAddress(&p, g_qkv);    p_qkv    = (float*)p;
        cudaGetSymbolAddress(&p, g_x2);     p_x2     = (float*)p;
        cudaGetSymbolAddress(&p, g_act_hi); p_act_h  = (__nv_bfloat16*)p;
        cudaGetSymbolAddress(&p, g_act_lo); p_act_l  = (__nv_bfloat16*)p;
        cudaGetSymbolAddress(&p, g_big_hi); p_big_h  = (__nv_bfloat16*)p;
        cudaGetSymbolAddress(&p, g_big_lo); p_big_l  = (__nv_bfloat16*)p;
        cudaGetSymbolAddress(&p, g_wqkv_h); p_wqkv_h = (__nv_bfloat16*)p;
        cudaGetSymbolAddress(&p, g_wqkv_l); p_wqkv_l = (__nv_bfloat16*)p;
        cudaGetSymbolAddress(&p, g_wo_h);   p_wo_h   = (__nv_bfloat16*)p;
        cudaGetSymbolAddress(&p, g_wo_l);   p_wo_l   = (__nv_bfloat16*)p;
        cudaGetSymbolAddress(&p, g_w1_h);   p_w1_h   = (__nv_bfloat16*)p;
        cudaGetSymbolAddress(&p, g_w1_l);   p_w1_l   = (__nv_bfloat16*)p;
        cudaGetSymbolAddress(&p, g_w2_h);   p_w2_h   = (__nv_bfloat16*)p;
        cudaGetSymbolAddress(&p, g_w2_l);   p_w2_l   = (__nv_bfloat16*)p;
        cudaFuncSetAttribute(gemm_tc<EPI_BIAS>,       cudaFuncAttributeMaxDynamicSharedMemorySize, SMEM_GEMM);
        cudaFuncSetAttribute(gemm_tc<EPI_BIAS_RES>,   cudaFuncAttributeMaxDynamicSharedMemorySize, SMEM_GEMM);
        cudaFuncSetAttribute(gemm_tc<EPI_GELU_SPLIT>, cudaFuncAttributeMaxDynamicSharedMemorySize, SMEM_GEMM);
        inited = true;
    }

    // 0. weight splits -> tiled bf16 hi/lo
    split_kernel<<<(3*D_*D_/4 + 255)/256, 256>>>(w_qkv, p_wqkv_h, p_wqkv_l, 3*D_*D_/4, D_);
    split_kernel<<<(D_*D_/4   + 255)/256, 256>>>(w_o,   p_wo_h,   p_wo_l,   D_*D_/4,   D_);
    split_kernel<<<(FF_*D_/4  + 255)/256, 256>>>(w1,    p_w1_h,   p_w1_l,   FF_*D_/4,  D_);
    split_kernel<<<(D_*FF_/4  + 255)/256, 256>>>(w2,    p_w2_h,   p_w2_l,   D_*FF_/4,  FF_);

    // 1. LN1 + split (tiled)
    ln_split_kernel<<<TOK, 256>>>(x, ln1_g, ln1_b, p_act_h, p_act_l);

    // 2. QKV projection
    gemm_tc<EPI_BIAS><<<dim3(3*D_/256, TOK/128), 256, SMEM_GEMM>>>(
        p_act_h, p_act_l, p_wqkv_h, p_wqkv_l, b_qkv, nullptr,
        p_qkv, nullptr, nullptr, 3*D_, D_);

    // 3. causal attention (tiled split output)
    attn_kernel<<<dim3(S_/128, B_*H_), 128>>>(p_qkv, p_act_h, p_act_l);

    // 4. output projection + residual
    gemm_tc<EPI_BIAS_RES><<<dim3(D_/256, TOK/128), 256, SMEM_GEMM>>>(
        p_act_h, p_act_l, p_wo_h, p_wo_l, b_o, x,
        p_x2, nullptr, nullptr, D_, D_);

    // 5. LN2 + split (tiled)
    ln_split_kernel<<<TOK, 256>>>(p_x2, ln2_g, ln2_b, p_act_h, p_act_l);

    // 6. FFN up + GELU + split (tiled)
    gemm_tc<EPI_GELU_SPLIT><<<dim3(FF_/256, TOK/128), 256, SMEM_GEMM>>>(
        p_act_h, p_act_l, p_w1_h, p_w1_l, b1, nullptr,
        nullptr, p_big_h, p_big_l, FF_, D_);

    // 7. FFN down + residual -> out
    gemm_tc<EPI_BIAS_RES><<<dim3(D_/256, TOK/128), 256, SMEM_GEMM>>>(
        p_big_h, p_big_l, p_w2_h, p_w2_l, b2, p_x2,
        out, nullptr, nullptr, D_, FF_);
}